// round 13
// baseline (speedup 1.0000x reference)
#include <cuda_runtime.h>
#include <cuda_bf16.h>
#include <math.h>
#include <stdint.h>

#define NN    1024
#define NE    4096
#define D     256
#define HN    4
#define DHD   64
#define NODEK 512
#define EDGEK 2048
#define CLS   16
#define MAXC  1024

// full-K resident GEMM: CTA 128x64, K=256, 8 warps (4m x 2n), warp 32x32
#define FAPITCH 264
#define F_AHI 0
#define F_ALO (128 * FAPITCH)
#define F_BHI (2 * 128 * FAPITCH)
#define F_BLO (2 * 128 * FAPITCH + 64 * FAPITCH)
#define F_ELEMS (2 * 128 * FAPITCH + 2 * 64 * FAPITCH)
#define F_BYTES (F_ELEMS * 2)   // 202752 B -> 1 CTA/SM (grid = 128 <= 148: one wave)

// ---------------- scratch ----------------
__device__ float g_nscore[NN];
__device__ float g_escore[NE];
__device__ int   g_nmask[NN];
__device__ int   g_emask[NE];
__device__ int   g_src[NE], g_dst[NE];
__device__ int   g_off[NN + 1];
__device__ int   g_inc[2 * NE];
__device__ float g_q[NE * D];
__device__ float g_k[NE * D];
__device__ float g_v[NE * D];
// split-bf16 activations (hi + residual lo)
__device__ __nv_bfloat16 g_hhi[NE * D],   g_hlo[NE * D];    // pair 0
__device__ __nv_bfloat16 g_aohi[NE * D],  g_aolo[NE * D];   // pair 1
__device__ __nv_bfloat16 g_ohi[NE * D],   g_olo[NE * D];    // pair 2
__device__ __nv_bfloat16 g_hidhi[NE * D], g_hidlo[NE * D];  // pair 3
// transposed split-bf16 weights: [w][n][k], w: 0=Wnp 1=Wq 2=Wk 3=Wv 4=Wo 5=W1
__device__ __nv_bfloat16 g_wthi[6 * D * D];
__device__ __nv_bfloat16 g_wtlo[6 * D * D];

template <int ID> __device__ __forceinline__ __nv_bfloat16* bufhi();
template <> __device__ __forceinline__ __nv_bfloat16* bufhi<0>() { return g_hhi; }
template <> __device__ __forceinline__ __nv_bfloat16* bufhi<1>() { return g_aohi; }
template <> __device__ __forceinline__ __nv_bfloat16* bufhi<2>() { return g_ohi; }
template <> __device__ __forceinline__ __nv_bfloat16* bufhi<3>() { return g_hidhi; }
template <int ID> __device__ __forceinline__ __nv_bfloat16* buflo();
template <> __device__ __forceinline__ __nv_bfloat16* buflo<0>() { return g_hlo; }
template <> __device__ __forceinline__ __nv_bfloat16* buflo<1>() { return g_aolo; }
template <> __device__ __forceinline__ __nv_bfloat16* buflo<2>() { return g_olo; }
template <> __device__ __forceinline__ __nv_bfloat16* buflo<3>() { return g_hidlo; }

// ================= 1: fused front-end =================
__global__ void k_front(const float* __restrict__ nf, const float* __restrict__ efi,
                        const int* __restrict__ ei,
                        const float* __restrict__ Wn, const float* __restrict__ bn,
                        const float* __restrict__ We, const float* __restrict__ be,
                        const float* __restrict__ Wnp, const float* __restrict__ Wq,
                        const float* __restrict__ Wk, const float* __restrict__ Wv,
                        const float* __restrict__ Wo, const float* __restrict__ W1) {
    int b = blockIdx.x;
    int tid = threadIdx.x;
    if (b < 96) {
        __shared__ float s[64][65];
        int w = b >> 4, t16 = b & 15;
        const float* W;
        switch (w) {
            case 0: W = Wnp; break;
            case 1: W = Wq; break;
            case 2: W = Wk; break;
            case 3: W = Wv; break;
            case 4: W = Wo; break;
            default: W = W1; break;
        }
        int n0 = (t16 & 3) * 64, k0 = (t16 >> 2) * 64;
        int n4 = (tid & 15) * 4, kr = tid >> 4;
        #pragma unroll
        for (int kk = kr; kk < 64; kk += 16) {
            float4 v = *(const float4*)&W[(size_t)(k0 + kk) * D + n0 + n4];
            s[kk][n4] = v.x;
            s[kk][n4 + 1] = v.y;
            s[kk][n4 + 2] = v.z;
            s[kk][n4 + 3] = v.w;
        }
        __syncthreads();
        int nl = tid >> 2, kq = (tid & 3) * 16;
        __nv_bfloat16 hi[16], lo[16];
        #pragma unroll
        for (int i = 0; i < 16; ++i) {
            float x = s[kq + i][nl];
            hi[i] = __float2bfloat16(x);
            lo[i] = __float2bfloat16(x - __bfloat162float(hi[i]));
        }
        size_t off = (size_t)w * D * D + (size_t)(n0 + nl) * D + k0 + kq;
        *(uint4*)&g_wthi[off] = *(uint4*)&hi[0];
        *(uint4*)&g_wthi[off + 8] = *(uint4*)&hi[8];
        *(uint4*)&g_wtlo[off] = *(uint4*)&lo[0];
        *(uint4*)&g_wtlo[off + 8] = *(uint4*)&lo[8];
    } else if (b < 112) {
        __shared__ int sh[256];
        int acc = 0;
        for (int i = tid; i < 2048; i += 256) acc |= ei[2 * i + 1];
        sh[tid] = acc;
        __syncthreads();
        for (int s2 = 128; s2 > 0; s2 >>= 1) {
            if (tid < s2) sh[tid] |= sh[tid + s2];
            __syncthreads();
        }
        int is64 = (sh[0] == 0) ? 1 : 0;
        int i = (b - 96) * 256 + tid;
        int s, d;
        if (is64) { s = ei[2 * i]; d = ei[2 * (NE + i)]; }
        else      { s = ei[i];     d = ei[NE + i]; }
        g_src[i] = s;
        g_dst[i] = d;
    } else {
        int warp = (b - 112) * 8 + (tid >> 5);
        int lane = tid & 31;
        const float* x;
        const float* w;
        if (warp < NN) { x = nf + (size_t)warp * D; w = Wn; }
        else           { x = efi + (size_t)(warp - NN) * D; w = We; }
        float s = 0.f;
        #pragma unroll
        for (int i = 0; i < D / 32; ++i) s += x[lane + i * 32] * w[lane + i * 32];
        #pragma unroll
        for (int o = 16; o; o >>= 1) s += __shfl_xor_sync(0xffffffffu, s, o);
        if (lane == 0) {
            if (warp < NN) g_nscore[warp] = s + bn[0];
            else           g_escore[warp - NN] = s + be[0];
        }
    }
}

// ================= 2: fused build =================
struct TkSmem {
    unsigned su[NE];
    int hist[256];
    unsigned pref;
    int krem;
    int wagg[32];
};
struct IncSmem {
    int cnt[NN];
    int off[NN];
    int pos[NN];
    int inc[2 * NE];
};
union BuildSmem {
    TkSmem tk;
    IncSmem in;
};

__global__ void __launch_bounds__(1024, 1) k_build() {
    __shared__ BuildSmem sm;
    int tid = threadIdx.x;
    int lane = tid & 31, wid = tid >> 5;

    if (blockIdx.x < 2) {
        const bool is_edge = (blockIdx.x == 1);
        const float* sc = is_edge ? g_escore : g_nscore;
        int* mask = is_edge ? g_emask : g_nmask;
        const int n = is_edge ? NE : NN;
        const int kk = is_edge ? EDGEK : NODEK;
        int items = n >> 10;

        for (int j = 0; j < items; ++j) {
            int i = tid * items + j;
            unsigned bb = __float_as_uint(sc[i]);
            sm.tk.su[i] = (bb & 0x80000000u) ? ~bb : (bb | 0x80000000u);
        }
        if (tid == 0) { sm.tk.pref = 0u; sm.tk.krem = kk; }
        __syncthreads();

        for (int shift = 24; shift >= 0; shift -= 8) {
            unsigned prefix = sm.tk.pref;
            unsigned done_mask = (shift == 24) ? 0u : (0xFFFFFFFFu << (shift + 8));
            if (tid < 256) sm.tk.hist[tid] = 0;
            __syncthreads();
            for (int j = 0; j < items; ++j) {
                unsigned u = sm.tk.su[tid * items + j];
                if ((u & done_mask) == prefix)
                    atomicAdd(&sm.tk.hist[(u >> shift) & 255], 1);
            }
            __syncthreads();
            if (wid == 0) {
                int krem = sm.tk.krem;
                int gsum = 0;
                #pragma unroll
                for (int c = 0; c < 8; ++c) gsum += sm.tk.hist[lane * 8 + c];
                int x = gsum;
                #pragma unroll
                for (int off = 1; off < 32; off <<= 1) {
                    int t = __shfl_down_sync(0xffffffffu, x, off);
                    if (lane + off < 32) x += t;
                }
                int above = x - gsum;
                bool hit = (above < krem) && (x >= krem);
                unsigned bal = __ballot_sync(0xffffffffu, hit);
                int srcl = __ffs(bal) - 1;
                if (lane == srcl) {
                    int cum = above;
                    #pragma unroll
                    for (int c = 7; c >= 0; --c) {
                        int bb = lane * 8 + c;
                        int hc = sm.tk.hist[bb];
                        if (cum + hc >= krem) {
                            sm.tk.pref = prefix | ((unsigned)bb << shift);
                            sm.tk.krem = krem - cum;
                            break;
                        }
                        cum += hc;
                    }
                }
            }
            __syncthreads();
        }
        unsigned T = sm.tk.pref;
        int r = sm.tk.krem;

        int ct = 0;
        for (int j = 0; j < items; ++j) ct += (sm.tk.su[tid * items + j] == T) ? 1 : 0;
        int scan = ct;
        #pragma unroll
        for (int off = 1; off < 32; off <<= 1) {
            int t = __shfl_up_sync(0xffffffffu, scan, off);
            if (lane >= off) scan += t;
        }
        if (lane == 31) sm.tk.wagg[wid] = scan;
        __syncthreads();
        if (wid == 0) {
            int v = sm.tk.wagg[lane];
            #pragma unroll
            for (int off = 1; off < 32; off <<= 1) {
                int t = __shfl_up_sync(0xffffffffu, v, off);
                if (lane >= off) v += t;
            }
            sm.tk.wagg[lane] = v;
        }
        __syncthreads();
        int excl = (wid > 0 ? sm.tk.wagg[wid - 1] : 0) + scan - ct;

        for (int j = 0; j < items; ++j) {
            int i = tid * items + j;
            unsigned u = sm.tk.su[i];
            int mk;
            if (u > T) mk = 1;
            else if (u == T) { mk = (excl < r) ? 1 : 0; excl++; }
            else mk = 0;
            mask[i] = mk;
        }
    } else {
        sm.in.cnt[tid] = 0;
        __syncthreads();
        #pragma unroll
        for (int j = 0; j < 4; ++j) {
            int e = j * 1024 + tid;
            int a = g_src[e], b = g_dst[e];
            atomicAdd(&sm.in.cnt[a], 1);
            if (b != a) atomicAdd(&sm.in.cnt[b], 1);
        }
        __syncthreads();
        int own = sm.in.cnt[tid];
        int val = own;
        for (int dd = 1; dd < 1024; dd <<= 1) {
            int t = (tid >= dd) ? sm.in.cnt[tid - dd] : 0;
            __syncthreads();
            val += t;
            sm.in.cnt[tid] = val;
            __syncthreads();
        }
        int offv = val - own;
        sm.in.off[tid] = offv;
        sm.in.pos[tid] = offv;
        if (tid == 1023) g_off[1024] = val;
        g_off[tid] = offv;
        __syncthreads();
        int total = sm.in.cnt[1023];
        #pragma unroll
        for (int j = 0; j < 4; ++j) {
            int e = j * 1024 + tid;
            int a = g_src[e], b = g_dst[e];
            sm.in.inc[atomicAdd(&sm.in.pos[a], 1)] = e;
            if (b != a) sm.in.inc[atomicAdd(&sm.in.pos[b], 1)] = e;
        }
        __syncthreads();
        {
            int s = sm.in.off[tid];
            int t = sm.in.pos[tid];
            for (int i = s + 1; i < t; ++i) {
                int v = sm.in.inc[i];
                int j = i - 1;
                while (j >= s && sm.in.inc[j] > v) { sm.in.inc[j + 1] = sm.in.inc[j]; --j; }
                sm.in.inc[j + 1] = v;
            }
        }
        __syncthreads();
        for (int i = tid; i < total; i += 1024) g_inc[i] = sm.in.inc[i];
    }
}

// ================= GEMM primitives =================
__device__ __forceinline__ void mma_bf16(float* c, const uint32_t* a, const uint32_t* b) {
    asm volatile(
        "mma.sync.aligned.m16n8k16.row.col.f32.bf16.bf16.f32 "
        "{%0,%1,%2,%3}, {%4,%5,%6,%7}, {%8,%9}, {%0,%1,%2,%3};"
        : "+f"(c[0]), "+f"(c[1]), "+f"(c[2]), "+f"(c[3])
        : "r"(a[0]), "r"(a[1]), "r"(a[2]), "r"(a[3]), "r"(b[0]), "r"(b[1]));
}

__device__ __forceinline__ void ldm_x4(uint32_t* r, uint32_t addr) {
    asm volatile("ldmatrix.sync.aligned.m8n8.x4.shared.b16 {%0,%1,%2,%3}, [%4];"
                 : "=r"(r[0]), "=r"(r[1]), "=r"(r[2]), "=r"(r[3]) : "r"(addr));
}

__device__ __forceinline__ void cp16(uint32_t s, const void* g) {
    asm volatile("cp.async.cg.shared.global [%0], [%1], 16;" :: "r"(s), "l"(g));
}
__device__ __forceinline__ void cp_commit() {
    asm volatile("cp.async.commit_group;" ::: "memory");
}
__device__ __forceinline__ void cp_wait0() {
    asm volatile("cp.async.wait_group 0;" ::: "memory");
}
__device__ __forceinline__ void cp_wait1() {
    asm volatile("cp.async.wait_group 1;" ::: "memory");
}

__device__ __forceinline__ void split_store_a(__nv_bfloat16* as_hi, __nv_bfloat16* as_lo,
                                              int o, float4 a) {
    __nv_bfloat16 h0 = __float2bfloat16(a.x), h1 = __float2bfloat16(a.y);
    __nv_bfloat16 h2 = __float2bfloat16(a.z), h3 = __float2bfloat16(a.w);
    __nv_bfloat16 l0 = __float2bfloat16(a.x - __bfloat162float(h0));
    __nv_bfloat16 l1 = __float2bfloat16(a.y - __bfloat162float(h1));
    __nv_bfloat16 l2 = __float2bfloat16(a.z - __bfloat162float(h2));
    __nv_bfloat16 l3 = __float2bfloat16(a.w - __bfloat162float(h3));
    *(__nv_bfloat162*)&as_hi[o]     = __nv_bfloat162(h0, h1);
    *(__nv_bfloat162*)&as_hi[o + 2] = __nv_bfloat162(h2, h3);
    *(__nv_bfloat162*)&as_lo[o]     = __nv_bfloat162(l0, l1);
    *(__nv_bfloat162*)&as_lo[o + 2] = __nv_bfloat162(l2, l3);
}

// async copy A half [128 x 128] (hi+lo): kh selects k in [kh*128, kh*128+128)
__device__ __forceinline__ void cp_a_half(uint32_t ah_u, uint32_t al_u,
                                          const __nv_bfloat16* Ahi, const __nv_bfloat16* Alo,
                                          int m0, int tid, int kh) {
    int kb = kh * 128;
    #pragma unroll
    for (int it = 0; it < 8; ++it) {
        int idx = it * 256 + tid;
        int m = idx >> 4, kq = kb + (idx & 15) * 8;
        uint32_t so = (uint32_t)((m * FAPITCH + kq) * 2);
        cp16(ah_u + so, &Ahi[(size_t)(m0 + m) * D + kq]);
        cp16(al_u + so, &Alo[(size_t)(m0 + m) * D + kq]);
    }
}

// async copy B [64 x 256] (hi+lo) for weight wslot
__device__ __forceinline__ void cp_b_full(uint32_t bh_u, uint32_t bl_u,
                                          int wslot, int n0, int tid) {
    const __nv_bfloat16* Bh = g_wthi + (size_t)wslot * D * D;
    const __nv_bfloat16* Bl = g_wtlo + (size_t)wslot * D * D;
    #pragma unroll
    for (int it = 0; it < 8; ++it) {
        int idx = it * 256 + tid;
        int n = idx >> 5, kq = (idx & 31) * 8;
        uint32_t so = (uint32_t)((n * FAPITCH + kq) * 2);
        cp16(bh_u + so, &Bh[(size_t)(n0 + n) * D + kq]);
        cp16(bl_u + so, &Bl[(size_t)(n0 + n) * D + kq]);
    }
}

// load all 8 fragments for one k-step: f[0..1]=A_hi, f[2..3]=A_lo, f[4..5]=B_hi, f[6..7]=B_lo
__device__ __forceinline__ void ld_frags(uint32_t ah_u, uint32_t al_u,
                                         uint32_t bh_u, uint32_t bl_u,
                                         uint32_t aoff0, uint32_t aoff1,
                                         uint32_t boff0, uint32_t boff1,
                                         uint32_t kb2, uint32_t f[8][4]) {
    ldm_x4(f[0], ah_u + aoff0 + kb2);
    ldm_x4(f[1], ah_u + aoff1 + kb2);
    ldm_x4(f[2], al_u + aoff0 + kb2);
    ldm_x4(f[3], al_u + aoff1 + kb2);
    ldm_x4(f[4], bh_u + boff0 + kb2);
    ldm_x4(f[5], bh_u + boff1 + kb2);
    ldm_x4(f[6], bl_u + boff0 + kb2);
    ldm_x4(f[7], bl_u + boff1 + kb2);
}

// term-major MMA issue: 8 independent HMMAs between writes to the same accumulator
__device__ __forceinline__ void issue_mmas(uint32_t f[8][4], float acc[2][4][4]) {
    #pragma unroll
    for (int mf = 0; mf < 2; ++mf)
        #pragma unroll
        for (int nf = 0; nf < 4; ++nf)
            mma_bf16(acc[mf][nf], f[mf], &f[4 + (nf >> 1)][(nf & 1) * 2]);      // hi*hi
    #pragma unroll
    for (int mf = 0; mf < 2; ++mf)
        #pragma unroll
        for (int nf = 0; nf < 4; ++nf)
            mma_bf16(acc[mf][nf], f[mf], &f[6 + (nf >> 1)][(nf & 1) * 2]);      // hi*lo
    #pragma unroll
    for (int mf = 0; mf < 2; ++mf)
        #pragma unroll
        for (int nf = 0; nf < 4; ++nf)
            mma_bf16(acc[mf][nf], f[2 + mf], &f[4 + (nf >> 1)][(nf & 1) * 2]);  // lo*hi
}

// 8 k-steps, software-pipelined fragment double-buffer
__device__ __forceinline__ void mma_steps8(uint32_t ah_u, uint32_t al_u,
                                           uint32_t bh_u, uint32_t bl_u,
                                           int wm, int wn, int lane,
                                           int ks0, float acc[2][4][4]) {
    int a_row = wm * 32 + (lane & 15);
    int a_ko = (lane >> 4) << 3;
    uint32_t aoff0 = (uint32_t)((a_row * FAPITCH + a_ko) * 2);
    uint32_t aoff1 = (uint32_t)(((a_row + 16) * FAPITCH + a_ko) * 2);
    int b_row = wn * 32 + (lane & 7) + ((lane >> 4) << 3);
    int b_ko = ((lane >> 3) & 1) << 3;
    uint32_t boff0 = (uint32_t)((b_row * FAPITCH + b_ko) * 2);
    uint32_t boff1 = (uint32_t)(((b_row + 16) * FAPITCH + b_ko) * 2);

    uint32_t fr[2][8][4];
    ld_frags(ah_u, al_u, bh_u, bl_u, aoff0, aoff1, boff0, boff1,
             (uint32_t)(ks0 * 32), fr[0]);
    #pragma unroll
    for (int s = 0; s < 8; ++s) {
        if (s < 7)
            ld_frags(ah_u, al_u, bh_u, bl_u, aoff0, aoff1, boff0, boff1,
                     (uint32_t)((ks0 + s + 1) * 32), fr[(s + 1) & 1]);
        issue_mmas(fr[s & 1], acc);
    }
}

// ================= GEMM kernels =================
// generic split->split, 2-stage pipelined prologue
template <int ACT, int AID, int CID>
__global__ void __launch_bounds__(256) k_gemm_sp(int wslot, const float* __restrict__ bias) {
    extern __shared__ __nv_bfloat16 smx[];
    uint32_t base = (uint32_t)__cvta_generic_to_shared(smx);
    uint32_t ah_u = base + F_AHI * 2, al_u = base + F_ALO * 2;
    uint32_t bh_u = base + F_BHI * 2, bl_u = base + F_BLO * 2;

    int tid = threadIdx.x;
    int wid = tid >> 5, lane = tid & 31;
    int g = lane >> 2, t = lane & 3;
    int wm = wid >> 1, wn = wid & 1;
    int m0 = blockIdx.y * 128, n0 = blockIdx.x * 64;

    cp_b_full(bh_u, bl_u, wslot, n0, tid);
    cp_a_half(ah_u, al_u, bufhi<AID>(), buflo<AID>(), m0, tid, 0);
    cp_commit();
    cp_a_half(ah_u, al_u, bufhi<AID>(), buflo<AID>(), m0, tid, 1);
    cp_commit();

    float acc[2][4][4] = {};
    cp_wait1();
    __syncthreads();
    mma_steps8(ah_u, al_u, bh_u, bl_u, wm, wn, lane, 0, acc);
    cp_wait0();
    __syncthreads();
    mma_steps8(ah_u, al_u, bh_u, bl_u, wm, wn, lane, 8, acc);

    __nv_bfloat16* Chi = bufhi<CID>();
    __nv_bfloat16* Clo = buflo<CID>();
    #pragma unroll
    for (int mf = 0; mf < 2; ++mf) {
        int r0 = m0 + wm * 32 + mf * 16 + g;
        #pragma unroll
        for (int nf = 0; nf < 4; ++nf) {
            int c = n0 + wn * 32 + nf * 8 + 2 * t;
            float bb0 = bias[c], bb1 = bias[c + 1];
            #pragma unroll
            for (int half = 0; half < 2; ++half) {
                int r = r0 + half * 8;
                float v0 = acc[mf][nf][half * 2 + 0] + bb0;
                float v1 = acc[mf][nf][half * 2 + 1] + bb1;
                if (ACT == 1) {
                    float x0 = v0, x1 = v1;
                    float t0 = tanhf(0.7978845608028654f * (x0 + 0.044715f * x0 * x0 * x0));
                    float t1 = tanhf(0.7978845608028654f * (x1 + 0.044715f * x1 * x1 * x1));
                    v0 = 0.5f * x0 * (1.0f + t0);
                    v1 = 0.5f * x1 * (1.0f + t1);
                }
                __nv_bfloat16 h0 = __float2bfloat16(v0), h1 = __float2bfloat16(v1);
                __nv_bfloat16 l0 = __float2bfloat16(v0 - __bfloat162float(h0));
                __nv_bfloat16 l1 = __float2bfloat16(v1 - __bfloat162float(h1));
                *(__nv_bfloat162*)&Chi[(size_t)r * D + c] = __nv_bfloat162(h0, h1);
                *(__nv_bfloat162*)&Clo[(size_t)r * D + c] = __nv_bfloat162(l0, l1);
            }
        }
    }
}

// h GEMM: A computed on the fly (nf[src]+nf[dst]); B loads async behind it
__global__ void __launch_bounds__(256) k_gemm_h(const float* __restrict__ nf,
                                                const float* __restrict__ efi,
                                                const float* __restrict__ bias) {
    extern __shared__ __nv_bfloat16 smx[];
    __nv_bfloat16* as_hi = smx + F_AHI;
    __nv_bfloat16* as_lo = smx + F_ALO;
    uint32_t base = (uint32_t)__cvta_generic_to_shared(smx);
    uint32_t ah_u = base + F_AHI * 2, al_u = base + F_ALO * 2;
    uint32_t bh_u = base + F_BHI * 2, bl_u = base + F_BLO * 2;

    int tid = threadIdx.x;
    int wid = tid >> 5, lane = tid & 31;
    int g = lane >> 2, t = lane & 3;
    int wm = wid >> 1, wn = wid & 1;
    int m0 = blockIdx.y * 128, n0 = blockIdx.x * 64;

    cp_b_full(bh_u, bl_u, 0, n0, tid);
    cp_commit();
    #pragma unroll
    for (int it = 0; it < 32; ++it) {
        int idx = it * 256 + tid;
        int m = idx >> 6, k4 = (idx & 63) * 4;
        int e = m0 + m;
        int a = g_src[e], b = g_dst[e];
        float4 xa = *(const float4*)&nf[(size_t)a * D + k4];
        float4 xb = *(const float4*)&nf[(size_t)b * D + k4];
        float4 s = {xa.x + xb.x, xa.y + xb.y, xa.z + xb.z, xa.w + xb.w};
        split_store_a(as_hi, as_lo, m * FAPITCH + k4, s);
    }
    cp_wait0();
    __syncthreads();

    float acc[2][4][4] = {};
    mma_steps8(ah_u, al_u, bh_u, bl_u, wm, wn, lane, 0, acc);
    mma_steps8(ah_u, al_u, bh_u, bl_u, wm, wn, lane, 8, acc);

    #pragma unroll
    for (int mf = 0; mf < 2; ++mf) {
        int r0 = m0 + wm * 32 + mf * 16 + g;
        #pragma unroll
        for (int half = 0; half < 2; ++half) {
            int r = r0 + half * 8;
            int em = g_emask[r] & g_nmask[g_src[r]] & g_nmask[g_dst[r]];
            float fm = em ? 1.0f : 0.0f;
            #pragma unroll
            for (int nf = 0; nf < 4; ++nf) {
                int c = n0 + wn * 32 + nf * 8 + 2 * t;
                float v0 = acc[mf][nf][half * 2 + 0] + bias[c]
                         + fm * efi[(size_t)r * D + c];
                float v1 = acc[mf][nf][half * 2 + 1] + bias[c + 1]
                         + fm * efi[(size_t)r * D + c + 1];
                __nv_bfloat16 h0 = __float2bfloat16(v0), h1 = __float2bfloat16(v1);
                __nv_bfloat16 l0 = __float2bfloat16(v0 - __bfloat162float(h0));
                __nv_bfloat16 l1 = __float2bfloat16(v1 - __bfloat162float(h1));
                *(__nv_bfloat162*)&g_hhi[(size_t)r * D + c] = __nv_bfloat162(h0, h1);
                *(__nv_bfloat162*)&g_hlo[(size_t)r * D + c] = __nv_bfloat162(l0, l1);
            }
        }
    }
}

// fused q/k/v GEMM: A resident once; B(w+1) prefetch overlaps epilogue(w)
__global__ void __launch_bounds__(256) k_gemm_qkv(
        const float* __restrict__ bq, const float* __restrict__ bk,
        const float* __restrict__ bv) {
    extern __shared__ __nv_bfloat16 smx[];
    uint32_t base = (uint32_t)__cvta_generic_to_shared(smx);
    uint32_t ah_u = base + F_AHI * 2, al_u = base + F_ALO * 2;
    uint32_t bh_u = base + F_BHI * 2, bl_u = base + F_BLO * 2;

    int tid = threadIdx.x;
    int wid = tid >> 5, lane = tid & 31;
    int g = lane >> 2, t = lane & 3;
    int wm = wid >> 1, wn = wid & 1;
    int m0 = blockIdx.y * 128, n0 = blockIdx.x * 64;

    cp_b_full(bh_u, bl_u, 1, n0, tid);
    cp_a_half(ah_u, al_u, g_hhi, g_hlo, m0, tid, 0);
    cp_commit();
    cp_a_half(ah_u, al_u, g_hhi, g_hlo, m0, tid, 1);
    cp_commit();

    #pragma unroll
    for (int w = 0; w < 3; ++w) {
        float acc[2][4][4] = {};
        if (w == 0) {
            cp_wait1();
            __syncthreads();
            mma_steps8(ah_u, al_u, bh_u, bl_u, wm, wn, lane, 0, acc);
            cp_wait0();
            __syncthreads();
            mma_steps8(ah_u, al_u, bh_u, bl_u, wm, wn, lane, 8, acc);
        } else {
            mma_steps8(ah_u, al_u, bh_u, bl_u, wm, wn, lane, 0, acc);
            mma_steps8(ah_u, al_u, bh_u, bl_u, wm, wn, lane, 8, acc);
        }

        if (w < 2) {
            __syncthreads();
            cp_b_full(bh_u, bl_u, 2 + w, n0, tid);
            cp_commit();
        }

        const float* bias = (w == 0) ? bq : (w == 1) ? bk : bv;
        float* C = (w == 0) ? g_q : (w == 1) ? g_k : g_v;
        #pragma unroll
        for (int mf = 0; mf < 2; ++mf) {
            int r0 = m0 + wm * 32 + mf * 16 + g;
            #pragma unroll
            for (int nf = 0; nf < 4; ++nf) {
                int c = n0 + wn * 32 + nf * 8 + 2 * t;
                float bb0 = bias[c], bb1 = bias[c + 1];
                #pragma unroll
                for (int half = 0; half < 2; ++half) {
                    int r = r0 + half * 8;
                    float2 o2 = {acc[mf][nf][half * 2 + 0] + bb0,
                                 acc[mf][nf][half * 2 + 1] + bb1};
                    *(float2*)&C[(size_t)r * D + c] = o2;
                }
            }
        }
        if (w < 2) {
            cp_wait0();
            __syncthreads();
        }
    }
}

// ================= sparse masked attention (2-way ILP) =================
__global__ void k_attn() {
    __shared__ int s_cand[MAXC];
    __shared__ float s_sc[HN][MAXC];
    __shared__ int s_n;
    int e = blockIdx.x;
    int tid = threadIdx.x;
    int h = tid >> 5, lane = tid & 31;
    int a = g_src[e], b = g_dst[e];
    int oa = g_off[a];
    int na = g_off[a + 1] - oa;

    for (int i = tid; i < na; i += 128) s_cand[i] = g_inc[oa + i];

    if (tid < 32) {
        int cnt = na;
        if (b != a) {
            int ob = g_off[b];
            int nb = g_off[b + 1] - ob;
            for (int i0 = 0; i0 < nb; i0 += 32) {
                int i = i0 + lane;
                int f = 0, keep = 0;
                if (i < nb) {
                    f = g_inc[ob + i];
                    keep = (g_src[f] != a && g_dst[f] != a) ? 1 : 0;
                }
                unsigned bal = __ballot_sync(0xffffffffu, keep != 0);
                if (keep) {
                    int pos = cnt + __popc(bal & ((1u << lane) - 1u));
                    if (pos < MAXC) s_cand[pos] = f;
                }
                cnt += __popc(bal);
            }
        }
        if (lane == 0) s_n = (cnt < MAXC) ? cnt : MAXC;
    }
    __syncthreads();
    int nc = s_n;
    int base = e * D + h * DHD;

    float2 q2 = *(const float2*)&g_q[base + lane * 2];

    for (int c = 0; c < nc; c += 2) {
        int f0 = s_cand[c];
        float2 k0 = *(const float2*)&g_k[f0 * D + h * DHD + lane * 2];
        bool has1 = (c + 1 < nc);
        float2 k1 = {0.f, 0.f};
        if (has1) {
            int f1 = s_cand[c + 1];
            k1 = *(const float2*)&g_k[f1 * D + h * DHD + lane * 2];
        }
        float s0 = q2.x * k0.x + q2.y * k0.y;
        float s1 = q2.x * k1.x + q2.y * k1.y;
        #pragma unroll
        for (int o = 16; o; o >>= 1) {
            s0 += __shfl_xor_sync(0xffffffffu, s0, o);
            s1 += __shfl_xor_sync(0xffffffffu, s1, o);
        }
        if (lane == 0) {
            s_sc[h][c] = s0 * 0.125f;
            if (has1) s_sc[h][c + 1] = s1 * 0.125f;
        }
    }
    __syncwarp();

    float mx = -3.0e38f;
    for (int c = lane; c < nc; c += 32) mx = fmaxf(mx, s_sc[h][c]);
    #pragma unroll
    for (int o = 16; o; o >>= 1) mx = fmaxf(mx, __shfl_xor_sync(0xffffffffu, mx, o));
    float l = 0.f;
    for (int c = lane; c < nc; c += 32) {
        float p = __expf(s_sc[h][c] - mx);
        s_sc[h][c] = p;
        l += p;
    }
    #pragma unroll
    for (int o = 16; o; o >>= 1) l += __shfl_xor_sync(0xffffffffu, l, o);
    __syncwarp();

    float ax = 0.f, ay = 0.f;
    for (int c = 0; c < nc; c += 2) {
        float p0 = s_sc[h][c];
        float2 v0 = *(const float2*)&g_v[s_cand[c] * D + h * DHD + lane * 2];
        if (c + 1 < nc) {
            float p1 = s_sc[h][c + 1];
            float2 v1 = *(const float2*)&g_v[s_cand[c + 1] * D + h * DHD + lane * 2];
            ax += p0 * v0.x + p1 * v1.x;
            ay += p0 * v0.y + p1 * v1.y;
        } else {
            ax += p0 * v0.x;
            ay += p0 * v0.y;
        }
    }
    float inv = 1.f / l;
    float vx = ax * inv, vy = ay * inv;
    __nv_bfloat16 hx = __float2bfloat16(vx), hy = __float2bfloat16(vy);
    __nv_bfloat16 lx = __float2bfloat16(vx - __bfloat162float(hx));
    __nv_bfloat16 ly = __float2bfloat16(vy - __bfloat162float(hy));
    *(__nv_bfloat162*)&g_aohi[base + lane * 2] = __nv_bfloat162(hx, hy);
    *(__nv_bfloat162*)&g_aolo[base + lane * 2] = __nv_bfloat162(lx, ly);
}

// ================= classifier =================
__global__ void k_cls(const float* __restrict__ W2, const float* __restrict__ b2,
                      float* __restrict__ out) {
    int warp = (blockIdx.x * blockDim.x + threadIdx.x) >> 5;
    int lane = threadIdx.x & 31;
    if (warp >= NE) return;
    float x[8];
    #pragma unroll
    for (int i = 0; i < 8; ++i) {
        size_t id = (size_t)warp * D + lane + i * 32;
        x[i] = __bfloat162float(g_hidhi[id]) + __bfloat162float(g_hidlo[id]);
    }
    float res = 0.f;
    #pragma unroll
    for (int c = 0; c < CLS; ++c) {
        float s = 0.f;
        #pragma unroll
        for (int i = 0; i < 8; ++i) s += x[i] * W2[(size_t)(lane + i * 32) * CLS + c];
        #pragma unroll
        for (int o = 16; o; o >>= 1) s += __shfl_xor_sync(0xffffffffu, s, o);
        if (lane == c) res = s + b2[c];
    }
    if (lane < CLS) out[(size_t)warp * CLS + lane] = res;
}

// ================= host =================
extern "C" void kernel_launch(void* const* d_in, const int* in_sizes, int n_in,
                              void* d_out, int out_size) {
    const float* nf   = (const float*)d_in[0];
    const float* efi  = (const float*)d_in[1];
    const int*   ei   = (const int*)d_in[2];
    const float* Wn_r = (const float*)d_in[3];
    const float* bn_r = (const float*)d_in[4];
    const float* We_r = (const float*)d_in[5];
    const float* be_r = (const float*)d_in[6];
    const float* Wnp  = (const float*)d_in[7];
    const float* bnp  = (const float*)d_in[8];
    const float* Wq   = (const float*)d_in[9];
    const float* bq   = (const float*)d_in[10];
    const float* Wk   = (const float*)d_in[11];
    const float* bk   = (const float*)d_in[12];
    const float* Wv   = (const float*)d_in[13];
    const float* bv   = (const float*)d_in[14];
    const float* Wo   = (const float*)d_in[15];
    const float* bo   = (const float*)d_in[16];
    const float* W1   = (const float*)d_in[17];
    const float* b1   = (const float*)d_in[18];
    const float* W2   = (const float*)d_in[19];
    const float* b2   = (const float*)d_in[20];
    float* out = (float*)d_out;

    cudaFuncSetAttribute(k_gemm_h, cudaFuncAttributeMaxDynamicSharedMemorySize, F_BYTES);
    cudaFuncSetAttribute(k_gemm_qkv, cudaFuncAttributeMaxDynamicSharedMemorySize, F_BYTES);
    cudaFuncSetAttribute(k_gemm_sp<0, 1, 2>, cudaFuncAttributeMaxDynamicSharedMemorySize, F_BYTES);
    cudaFuncSetAttribute(k_gemm_sp<1, 2, 3>, cudaFuncAttributeMaxDynamicSharedMemorySize, F_BYTES);

    k_front<<<752, 256>>>(nf, efi, ei, Wn_r, bn_r, We_r, be_r, Wnp, Wq, Wk, Wv, Wo, W1);
    k_build<<<3, 1024>>>();

    dim3 gg(D / 64, NE / 128);      // (4, 32) = 128 CTAs: one wave
    k_gemm_h<<<gg, 256, F_BYTES>>>(nf, efi, bnp);            // h (split)
    k_gemm_qkv<<<gg, 256, F_BYTES>>>(bq, bk, bv);            // q,k,v fp32
    k_attn<<<NE, 128>>>();                                   // ao (split)
    k_gemm_sp<0, 1, 2><<<gg, 256, F_BYTES>>>(4, bo);         // o (split)
    k_gemm_sp<1, 2, 3><<<gg, 256, F_BYTES>>>(5, b1);         // hid (split)
    k_cls<<<(NE * 32 + 255) / 256, 256>>>(W2, b2, out);
}

// round 14
// speedup vs baseline: 1.0021x; 1.0021x over previous
#include <cuda_runtime.h>
#include <cuda_bf16.h>
#include <math.h>
#include <stdint.h>

#define NN    1024
#define NE    4096
#define D     256
#define HN    4
#define DHD   64
#define NODEK 512
#define EDGEK 2048
#define CLS   16
#define MAXC  1024

// full-K resident GEMM: CTA 128x64 tile, K=256, 16 warps (8m x 2n), warp 16x32
#define FAPITCH 264
#define F_AHI 0
#define F_ALO (128 * FAPITCH)
#define F_BHI (2 * 128 * FAPITCH)
#define F_BLO (2 * 128 * FAPITCH + 64 * FAPITCH)
#define F_ELEMS (2 * 128 * FAPITCH + 2 * 64 * FAPITCH)
#define F_BYTES (F_ELEMS * 2)   // 202752 B -> 1 CTA/SM; grid 128 <= 148: one wave
#define GT 512                  // GEMM CTA threads (16 warps)

// ---------------- scratch ----------------
__device__ float g_nscore[NN];
__device__ float g_escore[NE];
__device__ int   g_nmask[NN];
__device__ int   g_emask[NE];
__device__ int   g_src[NE], g_dst[NE];
__device__ int   g_off[NN + 1];
__device__ int   g_inc[2 * NE];
__device__ float g_q[NE * D];
__device__ float g_k[NE * D];
__device__ float g_v[NE * D];
// split-bf16 activations (hi + residual lo)
__device__ __nv_bfloat16 g_hhi[NE * D],   g_hlo[NE * D];    // pair 0
__device__ __nv_bfloat16 g_aohi[NE * D],  g_aolo[NE * D];   // pair 1
__device__ __nv_bfloat16 g_ohi[NE * D],   g_olo[NE * D];    // pair 2
__device__ __nv_bfloat16 g_hidhi[NE * D], g_hidlo[NE * D];  // pair 3
// transposed split-bf16 weights: [w][n][k], w: 0=Wnp 1=Wq 2=Wk 3=Wv 4=Wo 5=W1
__device__ __nv_bfloat16 g_wthi[6 * D * D];
__device__ __nv_bfloat16 g_wtlo[6 * D * D];

template <int ID> __device__ __forceinline__ __nv_bfloat16* bufhi();
template <> __device__ __forceinline__ __nv_bfloat16* bufhi<0>() { return g_hhi; }
template <> __device__ __forceinline__ __nv_bfloat16* bufhi<1>() { return g_aohi; }
template <> __device__ __forceinline__ __nv_bfloat16* bufhi<2>() { return g_ohi; }
template <> __device__ __forceinline__ __nv_bfloat16* bufhi<3>() { return g_hidhi; }
template <int ID> __device__ __forceinline__ __nv_bfloat16* buflo();
template <> __device__ __forceinline__ __nv_bfloat16* buflo<0>() { return g_hlo; }
template <> __device__ __forceinline__ __nv_bfloat16* buflo<1>() { return g_aolo; }
template <> __device__ __forceinline__ __nv_bfloat16* buflo<2>() { return g_olo; }
template <> __device__ __forceinline__ __nv_bfloat16* buflo<3>() { return g_hidlo; }

// ================= 1: fused front-end =================
__global__ void k_front(const float* __restrict__ nf, const float* __restrict__ efi,
                        const int* __restrict__ ei,
                        const float* __restrict__ Wn, const float* __restrict__ bn,
                        const float* __restrict__ We, const float* __restrict__ be,
                        const float* __restrict__ Wnp, const float* __restrict__ Wq,
                        const float* __restrict__ Wk, const float* __restrict__ Wv,
                        const float* __restrict__ Wo, const float* __restrict__ W1) {
    int b = blockIdx.x;
    int tid = threadIdx.x;
    if (b < 96) {
        __shared__ float s[64][65];
        int w = b >> 4, t16 = b & 15;
        const float* W;
        switch (w) {
            case 0: W = Wnp; break;
            case 1: W = Wq; break;
            case 2: W = Wk; break;
            case 3: W = Wv; break;
            case 4: W = Wo; break;
            default: W = W1; break;
        }
        int n0 = (t16 & 3) * 64, k0 = (t16 >> 2) * 64;
        int n4 = (tid & 15) * 4, kr = tid >> 4;
        #pragma unroll
        for (int kk = kr; kk < 64; kk += 16) {
            float4 v = *(const float4*)&W[(size_t)(k0 + kk) * D + n0 + n4];
            s[kk][n4] = v.x;
            s[kk][n4 + 1] = v.y;
            s[kk][n4 + 2] = v.z;
            s[kk][n4 + 3] = v.w;
        }
        __syncthreads();
        int nl = tid >> 2, kq = (tid & 3) * 16;
        __nv_bfloat16 hi[16], lo[16];
        #pragma unroll
        for (int i = 0; i < 16; ++i) {
            float x = s[kq + i][nl];
            hi[i] = __float2bfloat16(x);
            lo[i] = __float2bfloat16(x - __bfloat162float(hi[i]));
        }
        size_t off = (size_t)w * D * D + (size_t)(n0 + nl) * D + k0 + kq;
        *(uint4*)&g_wthi[off] = *(uint4*)&hi[0];
        *(uint4*)&g_wthi[off + 8] = *(uint4*)&hi[8];
        *(uint4*)&g_wtlo[off] = *(uint4*)&lo[0];
        *(uint4*)&g_wtlo[off + 8] = *(uint4*)&lo[8];
    } else if (b < 112) {
        __shared__ int sh[256];
        int acc = 0;
        for (int i = tid; i < 2048; i += 256) acc |= ei[2 * i + 1];
        sh[tid] = acc;
        __syncthreads();
        for (int s2 = 128; s2 > 0; s2 >>= 1) {
            if (tid < s2) sh[tid] |= sh[tid + s2];
            __syncthreads();
        }
        int is64 = (sh[0] == 0) ? 1 : 0;
        int i = (b - 96) * 256 + tid;
        int s, d;
        if (is64) { s = ei[2 * i]; d = ei[2 * (NE + i)]; }
        else      { s = ei[i];     d = ei[NE + i]; }
        g_src[i] = s;
        g_dst[i] = d;
    } else {
        int warp = (b - 112) * 8 + (tid >> 5);
        int lane = tid & 31;
        const float* x;
        const float* w;
        if (warp < NN) { x = nf + (size_t)warp * D; w = Wn; }
        else           { x = efi + (size_t)(warp - NN) * D; w = We; }
        float s = 0.f;
        #pragma unroll
        for (int i = 0; i < D / 32; ++i) s += x[lane + i * 32] * w[lane + i * 32];
        #pragma unroll
        for (int o = 16; o; o >>= 1) s += __shfl_xor_sync(0xffffffffu, s, o);
        if (lane == 0) {
            if (warp < NN) g_nscore[warp] = s + bn[0];
            else           g_escore[warp - NN] = s + be[0];
        }
    }
}

// ================= 2: fused build =================
struct TkSmem {
    unsigned su[NE];
    int hist[256];
    unsigned pref;
    int krem;
    int wagg[32];
};
struct IncSmem {
    int cnt[NN];
    int off[NN];
    int pos[NN];
    int inc[2 * NE];
};
union BuildSmem {
    TkSmem tk;
    IncSmem in;
};

__global__ void __launch_bounds__(1024, 1) k_build() {
    __shared__ BuildSmem sm;
    int tid = threadIdx.x;
    int lane = tid & 31, wid = tid >> 5;

    if (blockIdx.x < 2) {
        const bool is_edge = (blockIdx.x == 1);
        const float* sc = is_edge ? g_escore : g_nscore;
        int* mask = is_edge ? g_emask : g_nmask;
        const int n = is_edge ? NE : NN;
        const int kk = is_edge ? EDGEK : NODEK;
        int items = n >> 10;

        for (int j = 0; j < items; ++j) {
            int i = tid * items + j;
            unsigned bb = __float_as_uint(sc[i]);
            sm.tk.su[i] = (bb & 0x80000000u) ? ~bb : (bb | 0x80000000u);
        }
        if (tid == 0) { sm.tk.pref = 0u; sm.tk.krem = kk; }
        __syncthreads();

        for (int shift = 24; shift >= 0; shift -= 8) {
            unsigned prefix = sm.tk.pref;
            unsigned done_mask = (shift == 24) ? 0u : (0xFFFFFFFFu << (shift + 8));
            if (tid < 256) sm.tk.hist[tid] = 0;
            __syncthreads();
            for (int j = 0; j < items; ++j) {
                unsigned u = sm.tk.su[tid * items + j];
                if ((u & done_mask) == prefix)
                    atomicAdd(&sm.tk.hist[(u >> shift) & 255], 1);
            }
            __syncthreads();
            if (wid == 0) {
                int krem = sm.tk.krem;
                int gsum = 0;
                #pragma unroll
                for (int c = 0; c < 8; ++c) gsum += sm.tk.hist[lane * 8 + c];
                int x = gsum;
                #pragma unroll
                for (int off = 1; off < 32; off <<= 1) {
                    int t = __shfl_down_sync(0xffffffffu, x, off);
                    if (lane + off < 32) x += t;
                }
                int above = x - gsum;
                bool hit = (above < krem) && (x >= krem);
                unsigned bal = __ballot_sync(0xffffffffu, hit);
                int srcl = __ffs(bal) - 1;
                if (lane == srcl) {
                    int cum = above;
                    #pragma unroll
                    for (int c = 7; c >= 0; --c) {
                        int bb = lane * 8 + c;
                        int hc = sm.tk.hist[bb];
                        if (cum + hc >= krem) {
                            sm.tk.pref = prefix | ((unsigned)bb << shift);
                            sm.tk.krem = krem - cum;
                            break;
                        }
                        cum += hc;
                    }
                }
            }
            __syncthreads();
        }
        unsigned T = sm.tk.pref;
        int r = sm.tk.krem;

        int ct = 0;
        for (int j = 0; j < items; ++j) ct += (sm.tk.su[tid * items + j] == T) ? 1 : 0;
        int scan = ct;
        #pragma unroll
        for (int off = 1; off < 32; off <<= 1) {
            int t = __shfl_up_sync(0xffffffffu, scan, off);
            if (lane >= off) scan += t;
        }
        if (lane == 31) sm.tk.wagg[wid] = scan;
        __syncthreads();
        if (wid == 0) {
            int v = sm.tk.wagg[lane];
            #pragma unroll
            for (int off = 1; off < 32; off <<= 1) {
                int t = __shfl_up_sync(0xffffffffu, v, off);
                if (lane >= off) v += t;
            }
            sm.tk.wagg[lane] = v;
        }
        __syncthreads();
        int excl = (wid > 0 ? sm.tk.wagg[wid - 1] : 0) + scan - ct;

        for (int j = 0; j < items; ++j) {
            int i = tid * items + j;
            unsigned u = sm.tk.su[i];
            int mk;
            if (u > T) mk = 1;
            else if (u == T) { mk = (excl < r) ? 1 : 0; excl++; }
            else mk = 0;
            mask[i] = mk;
        }
    } else {
        sm.in.cnt[tid] = 0;
        __syncthreads();
        #pragma unroll
        for (int j = 0; j < 4; ++j) {
            int e = j * 1024 + tid;
            int a = g_src[e], b = g_dst[e];
            atomicAdd(&sm.in.cnt[a], 1);
            if (b != a) atomicAdd(&sm.in.cnt[b], 1);
        }
        __syncthreads();
        int own = sm.in.cnt[tid];
        int val = own;
        for (int dd = 1; dd < 1024; dd <<= 1) {
            int t = (tid >= dd) ? sm.in.cnt[tid - dd] : 0;
            __syncthreads();
            val += t;
            sm.in.cnt[tid] = val;
            __syncthreads();
        }
        int offv = val - own;
        sm.in.off[tid] = offv;
        sm.in.pos[tid] = offv;
        if (tid == 1023) g_off[1024] = val;
        g_off[tid] = offv;
        __syncthreads();
        int total = sm.in.cnt[1023];
        #pragma unroll
        for (int j = 0; j < 4; ++j) {
            int e = j * 1024 + tid;
            int a = g_src[e], b = g_dst[e];
            sm.in.inc[atomicAdd(&sm.in.pos[a], 1)] = e;
            if (b != a) sm.in.inc[atomicAdd(&sm.in.pos[b], 1)] = e;
        }
        __syncthreads();
        {
            int s = sm.in.off[tid];
            int t = sm.in.pos[tid];
            for (int i = s + 1; i < t; ++i) {
                int v = sm.in.inc[i];
                int j = i - 1;
                while (j >= s && sm.in.inc[j] > v) { sm.in.inc[j + 1] = sm.in.inc[j]; --j; }
                sm.in.inc[j + 1] = v;
            }
        }
        __syncthreads();
        for (int i = tid; i < total; i += 1024) g_inc[i] = sm.in.inc[i];
    }
}

// ================= GEMM primitives =================
__device__ __forceinline__ void mma_bf16(float* c, const uint32_t* a, const uint32_t* b) {
    asm volatile(
        "mma.sync.aligned.m16n8k16.row.col.f32.bf16.bf16.f32 "
        "{%0,%1,%2,%3}, {%4,%5,%6,%7}, {%8,%9}, {%0,%1,%2,%3};"
        : "+f"(c[0]), "+f"(c[1]), "+f"(c[2]), "+f"(c[3])
        : "r"(a[0]), "r"(a[1]), "r"(a[2]), "r"(a[3]), "r"(b[0]), "r"(b[1]));
}

__device__ __forceinline__ void ldm_x4(uint32_t* r, uint32_t addr) {
    asm volatile("ldmatrix.sync.aligned.m8n8.x4.shared.b16 {%0,%1,%2,%3}, [%4];"
                 : "=r"(r[0]), "=r"(r[1]), "=r"(r[2]), "=r"(r[3]) : "r"(addr));
}

__device__ __forceinline__ void cp16(uint32_t s, const void* g) {
    asm volatile("cp.async.cg.shared.global [%0], [%1], 16;" :: "r"(s), "l"(g));
}
__device__ __forceinline__ void cp_commit() {
    asm volatile("cp.async.commit_group;" ::: "memory");
}
__device__ __forceinline__ void cp_wait0() {
    asm volatile("cp.async.wait_group 0;" ::: "memory");
}
__device__ __forceinline__ void cp_wait1() {
    asm volatile("cp.async.wait_group 1;" ::: "memory");
}

__device__ __forceinline__ void split_store_a(__nv_bfloat16* as_hi, __nv_bfloat16* as_lo,
                                              int o, float4 a) {
    __nv_bfloat16 h0 = __float2bfloat16(a.x), h1 = __float2bfloat16(a.y);
    __nv_bfloat16 h2 = __float2bfloat16(a.z), h3 = __float2bfloat16(a.w);
    __nv_bfloat16 l0 = __float2bfloat16(a.x - __bfloat162float(h0));
    __nv_bfloat16 l1 = __float2bfloat16(a.y - __bfloat162float(h1));
    __nv_bfloat16 l2 = __float2bfloat16(a.z - __bfloat162float(h2));
    __nv_bfloat16 l3 = __float2bfloat16(a.w - __bfloat162float(h3));
    *(__nv_bfloat162*)&as_hi[o]     = __nv_bfloat162(h0, h1);
    *(__nv_bfloat162*)&as_hi[o + 2] = __nv_bfloat162(h2, h3);
    *(__nv_bfloat162*)&as_lo[o]     = __nv_bfloat162(l0, l1);
    *(__nv_bfloat162*)&as_lo[o + 2] = __nv_bfloat162(l2, l3);
}

// async copy A half [128 x 128] (hi+lo): kh selects k in [kh*128, kh*128+128)  (GT threads)
__device__ __forceinline__ void cp_a_half(uint32_t ah_u, uint32_t al_u,
                                          const __nv_bfloat16* Ahi, const __nv_bfloat16* Alo,
                                          int m0, int tid, int kh) {
    int kb = kh * 128;
    #pragma unroll
    for (int it = 0; it < 4; ++it) {
        int idx = it * GT + tid;             // 2048 16B chunks per array per half
        int m = idx >> 4, kq = kb + (idx & 15) * 8;
        uint32_t so = (uint32_t)((m * FAPITCH + kq) * 2);
        cp16(ah_u + so, &Ahi[(size_t)(m0 + m) * D + kq]);
        cp16(al_u + so, &Alo[(size_t)(m0 + m) * D + kq]);
    }
}

// async copy B [64 x 256] (hi+lo) for weight wslot  (GT threads)
__device__ __forceinline__ void cp_b_full(uint32_t bh_u, uint32_t bl_u,
                                          int wslot, int n0, int tid) {
    const __nv_bfloat16* Bh = g_wthi + (size_t)wslot * D * D;
    const __nv_bfloat16* Bl = g_wtlo + (size_t)wslot * D * D;
    #pragma unroll
    for (int it = 0; it < 4; ++it) {
        int idx = it * GT + tid;             // 2048 16B chunks per array
        int n = idx >> 5, kq = (idx & 31) * 8;
        uint32_t so = (uint32_t)((n * FAPITCH + kq) * 2);
        cp16(bh_u + so, &Bh[(size_t)(n0 + n) * D + kq]);
        cp16(bl_u + so, &Bl[(size_t)(n0 + n) * D + kq]);
    }
}

// 16-warp layout: warp tile 16x32 (wm = wid>>1 in 0..7, wn = wid&1).
// frags per step: f[0]=A_hi, f[1]=A_lo, f[2..3]=B_hi(nf01,nf23), f[4..5]=B_lo
__device__ __forceinline__ void ld_frags6(uint32_t ah_u, uint32_t al_u,
                                          uint32_t bh_u, uint32_t bl_u,
                                          uint32_t aoff, uint32_t boff0, uint32_t boff1,
                                          uint32_t kb2, uint32_t f[6][4]) {
    ldm_x4(f[0], ah_u + aoff + kb2);
    ldm_x4(f[1], al_u + aoff + kb2);
    ldm_x4(f[2], bh_u + boff0 + kb2);
    ldm_x4(f[3], bh_u + boff1 + kb2);
    ldm_x4(f[4], bl_u + boff0 + kb2);
    ldm_x4(f[5], bl_u + boff1 + kb2);
}

__device__ __forceinline__ void issue_mmas6(uint32_t f[6][4], float acc[4][4]) {
    #pragma unroll
    for (int nf = 0; nf < 4; ++nf)
        mma_bf16(acc[nf], f[0], &f[2 + (nf >> 1)][(nf & 1) * 2]);   // hi*hi
    #pragma unroll
    for (int nf = 0; nf < 4; ++nf)
        mma_bf16(acc[nf], f[0], &f[4 + (nf >> 1)][(nf & 1) * 2]);   // hi*lo
    #pragma unroll
    for (int nf = 0; nf < 4; ++nf)
        mma_bf16(acc[nf], f[1], &f[2 + (nf >> 1)][(nf & 1) * 2]);   // lo*hi
}

// 8 k-steps, software-pipelined fragment double-buffer (16-warp layout)
__device__ __forceinline__ void mma_steps8(uint32_t ah_u, uint32_t al_u,
                                           uint32_t bh_u, uint32_t bl_u,
                                           int wm, int wn, int lane,
                                           int ks0, float acc[4][4]) {
    int a_row = wm * 16 + (lane & 15);
    int a_ko = (lane >> 4) << 3;
    uint32_t aoff = (uint32_t)((a_row * FAPITCH + a_ko) * 2);
    int b_row = wn * 32 + (lane & 7) + ((lane >> 4) << 3);
    int b_ko = ((lane >> 3) & 1) << 3;
    uint32_t boff0 = (uint32_t)((b_row * FAPITCH + b_ko) * 2);
    uint32_t boff1 = (uint32_t)(((b_row + 16) * FAPITCH + b_ko) * 2);

    uint32_t fr[2][6][4];
    ld_frags6(ah_u, al_u, bh_u, bl_u, aoff, boff0, boff1, (uint32_t)(ks0 * 32), fr[0]);
    #pragma unroll
    for (int s = 0; s < 8; ++s) {
        if (s < 7)
            ld_frags6(ah_u, al_u, bh_u, bl_u, aoff, boff0, boff1,
                      (uint32_t)((ks0 + s + 1) * 32), fr[(s + 1) & 1]);
        issue_mmas6(fr[s & 1], acc);
    }
}

// ================= GEMM kernels (512 threads, 16 warps) =================
template <int ACT, int AID, int CID>
__global__ void __launch_bounds__(GT) k_gemm_sp(int wslot, const float* __restrict__ bias) {
    extern __shared__ __nv_bfloat16 smx[];
    uint32_t base = (uint32_t)__cvta_generic_to_shared(smx);
    uint32_t ah_u = base + F_AHI * 2, al_u = base + F_ALO * 2;
    uint32_t bh_u = base + F_BHI * 2, bl_u = base + F_BLO * 2;

    int tid = threadIdx.x;
    int wid = tid >> 5, lane = tid & 31;
    int g = lane >> 2, t = lane & 3;
    int wm = wid >> 1, wn = wid & 1;
    int m0 = blockIdx.y * 128, n0 = blockIdx.x * 64;

    cp_b_full(bh_u, bl_u, wslot, n0, tid);
    cp_a_half(ah_u, al_u, bufhi<AID>(), buflo<AID>(), m0, tid, 0);
    cp_commit();
    cp_a_half(ah_u, al_u, bufhi<AID>(), buflo<AID>(), m0, tid, 1);
    cp_commit();

    float acc[4][4] = {};
    cp_wait1();
    __syncthreads();
    mma_steps8(ah_u, al_u, bh_u, bl_u, wm, wn, lane, 0, acc);
    cp_wait0();
    __syncthreads();
    mma_steps8(ah_u, al_u, bh_u, bl_u, wm, wn, lane, 8, acc);

    __nv_bfloat16* Chi = bufhi<CID>();
    __nv_bfloat16* Clo = buflo<CID>();
    int r0 = m0 + wm * 16 + g;
    #pragma unroll
    for (int nf = 0; nf < 4; ++nf) {
        int c = n0 + wn * 32 + nf * 8 + 2 * t;
        float bb0 = bias[c], bb1 = bias[c + 1];
        #pragma unroll
        for (int half = 0; half < 2; ++half) {
            int r = r0 + half * 8;
            float v0 = acc[nf][half * 2 + 0] + bb0;
            float v1 = acc[nf][half * 2 + 1] + bb1;
            if (ACT == 1) {
                float x0 = v0, x1 = v1;
                float t0 = tanhf(0.7978845608028654f * (x0 + 0.044715f * x0 * x0 * x0));
                float t1 = tanhf(0.7978845608028654f * (x1 + 0.044715f * x1 * x1 * x1));
                v0 = 0.5f * x0 * (1.0f + t0);
                v1 = 0.5f * x1 * (1.0f + t1);
            }
            __nv_bfloat16 h0 = __float2bfloat16(v0), h1 = __float2bfloat16(v1);
            __nv_bfloat16 l0 = __float2bfloat16(v0 - __bfloat162float(h0));
            __nv_bfloat16 l1 = __float2bfloat16(v1 - __bfloat162float(h1));
            *(__nv_bfloat162*)&Chi[(size_t)r * D + c] = __nv_bfloat162(h0, h1);
            *(__nv_bfloat162*)&Clo[(size_t)r * D + c] = __nv_bfloat162(l0, l1);
        }
    }
}

// h GEMM: A computed on the fly (nf[src]+nf[dst]); B loads async behind it
__global__ void __launch_bounds__(GT) k_gemm_h(const float* __restrict__ nf,
                                               const float* __restrict__ efi,
                                               const float* __restrict__ bias) {
    extern __shared__ __nv_bfloat16 smx[];
    __nv_bfloat16* as_hi = smx + F_AHI;
    __nv_bfloat16* as_lo = smx + F_ALO;
    uint32_t base = (uint32_t)__cvta_generic_to_shared(smx);
    uint32_t ah_u = base + F_AHI * 2, al_u = base + F_ALO * 2;
    uint32_t bh_u = base + F_BHI * 2, bl_u = base + F_BLO * 2;

    int tid = threadIdx.x;
    int wid = tid >> 5, lane = tid & 31;
    int g = lane >> 2, t = lane & 3;
    int wm = wid >> 1, wn = wid & 1;
    int m0 = blockIdx.y * 128, n0 = blockIdx.x * 64;

    cp_b_full(bh_u, bl_u, 0, n0, tid);
    cp_commit();
    #pragma unroll
    for (int it = 0; it < 16; ++it) {
        int idx = it * GT + tid;         // 8192 float4
        int m = idx >> 6, k4 = (idx & 63) * 4;
        int e = m0 + m;
        int a = g_src[e], b = g_dst[e];
        float4 xa = *(const float4*)&nf[(size_t)a * D + k4];
        float4 xb = *(const float4*)&nf[(size_t)b * D + k4];
        float4 s = {xa.x + xb.x, xa.y + xb.y, xa.z + xb.z, xa.w + xb.w};
        split_store_a(as_hi, as_lo, m * FAPITCH + k4, s);
    }
    cp_wait0();
    __syncthreads();

    float acc[4][4] = {};
    mma_steps8(ah_u, al_u, bh_u, bl_u, wm, wn, lane, 0, acc);
    mma_steps8(ah_u, al_u, bh_u, bl_u, wm, wn, lane, 8, acc);

    int r0 = m0 + wm * 16 + g;
    #pragma unroll
    for (int half = 0; half < 2; ++half) {
        int r = r0 + half * 8;
        int em = g_emask[r] & g_nmask[g_src[r]] & g_nmask[g_dst[r]];
        float fm = em ? 1.0f : 0.0f;
        #pragma unroll
        for (int nf2 = 0; nf2 < 4; ++nf2) {
            int c = n0 + wn * 32 + nf2 * 8 + 2 * t;
            float v0 = acc[nf2][half * 2 + 0] + bias[c] + fm * efi[(size_t)r * D + c];
            float v1 = acc[nf2][half * 2 + 1] + bias[c + 1] + fm * efi[(size_t)r * D + c + 1];
            __nv_bfloat16 h0 = __float2bfloat16(v0), h1 = __float2bfloat16(v1);
            __nv_bfloat16 l0 = __float2bfloat16(v0 - __bfloat162float(h0));
            __nv_bfloat16 l1 = __float2bfloat16(v1 - __bfloat162float(h1));
            *(__nv_bfloat162*)&g_hhi[(size_t)r * D + c] = __nv_bfloat162(h0, h1);
            *(__nv_bfloat162*)&g_hlo[(size_t)r * D + c] = __nv_bfloat162(l0, l1);
        }
    }
}

// fused q/k/v GEMM: A resident once; B(w+1) prefetch overlaps epilogue(w)
__global__ void __launch_bounds__(GT) k_gemm_qkv(
        const float* __restrict__ bq, const float* __restrict__ bk,
        const float* __restrict__ bv) {
    extern __shared__ __nv_bfloat16 smx[];
    uint32_t base = (uint32_t)__cvta_generic_to_shared(smx);
    uint32_t ah_u = base + F_AHI * 2, al_u = base + F_ALO * 2;
    uint32_t bh_u = base + F_BHI * 2, bl_u = base + F_BLO * 2;

    int tid = threadIdx.x;
    int wid = tid >> 5, lane = tid & 31;
    int g = lane >> 2, t = lane & 3;
    int wm = wid >> 1, wn = wid & 1;
    int m0 = blockIdx.y * 128, n0 = blockIdx.x * 64;

    cp_b_full(bh_u, bl_u, 1, n0, tid);
    cp_a_half(ah_u, al_u, g_hhi, g_hlo, m0, tid, 0);
    cp_commit();
    cp_a_half(ah_u, al_u, g_hhi, g_hlo, m0, tid, 1);
    cp_commit();

    #pragma unroll
    for (int w = 0; w < 3; ++w) {
        float acc[4][4] = {};
        if (w == 0) {
            cp_wait1();
            __syncthreads();
            mma_steps8(ah_u, al_u, bh_u, bl_u, wm, wn, lane, 0, acc);
            cp_wait0();
            __syncthreads();
            mma_steps8(ah_u, al_u, bh_u, bl_u, wm, wn, lane, 8, acc);
        } else {
            mma_steps8(ah_u, al_u, bh_u, bl_u, wm, wn, lane, 0, acc);
            mma_steps8(ah_u, al_u, bh_u, bl_u, wm, wn, lane, 8, acc);
        }

        if (w < 2) {
            __syncthreads();
            cp_b_full(bh_u, bl_u, 2 + w, n0, tid);
            cp_commit();
        }

        const float* bias = (w == 0) ? bq : (w == 1) ? bk : bv;
        float* C = (w == 0) ? g_q : (w == 1) ? g_k : g_v;
        int r0 = m0 + wm * 16 + g;
        #pragma unroll
        for (int nf = 0; nf < 4; ++nf) {
            int c = n0 + wn * 32 + nf * 8 + 2 * t;
            float bb0 = bias[c], bb1 = bias[c + 1];
            #pragma unroll
            for (int half = 0; half < 2; ++half) {
                int r = r0 + half * 8;
                float2 o2 = {acc[nf][half * 2 + 0] + bb0,
                             acc[nf][half * 2 + 1] + bb1};
                *(float2*)&C[(size_t)r * D + c] = o2;
            }
        }
        if (w < 2) {
            cp_wait0();
            __syncthreads();
        }
    }
}

// ================= sparse masked attention (2-way ILP) =================
__global__ void k_attn() {
    __shared__ int s_cand[MAXC];
    __shared__ float s_sc[HN][MAXC];
    __shared__ int s_n;
    int e = blockIdx.x;
    int tid = threadIdx.x;
    int h = tid >> 5, lane = tid & 31;
    int a = g_src[e], b = g_dst[e];
    int oa = g_off[a];
    int na = g_off[a + 1] - oa;

    for (int i = tid; i < na; i += 128) s_cand[i] = g_inc[oa + i];

    if (tid < 32) {
        int cnt = na;
        if (b != a) {
            int ob = g_off[b];
            int nb = g_off[b + 1] - ob;
            for (int i0 = 0; i0 < nb; i0 += 32) {
                int i = i0 + lane;
                int f = 0, keep = 0;
                if (i < nb) {
                    f = g_inc[ob + i];
                    keep = (g_src[f] != a && g_dst[f] != a) ? 1 : 0;
                }
                unsigned bal = __ballot_sync(0xffffffffu, keep != 0);
                if (keep) {
                    int pos = cnt + __popc(bal & ((1u << lane) - 1u));
                    if (pos < MAXC) s_cand[pos] = f;
                }
                cnt += __popc(bal);
            }
        }
        if (lane == 0) s_n = (cnt < MAXC) ? cnt : MAXC;
    }
    __syncthreads();
    int nc = s_n;
    int base = e * D + h * DHD;

    float2 q2 = *(const float2*)&g_q[base + lane * 2];

    for (int c = 0; c < nc; c += 2) {
        int f0 = s_cand[c];
        float2 k0 = *(const float2*)&g_k[f0 * D + h * DHD + lane * 2];
        bool has1 = (c + 1 < nc);
        float2 k1 = {0.f, 0.f};
        if (has1) {
            int f1 = s_cand[c + 1];
            k1 = *(const float2*)&g_k[f1 * D + h * DHD + lane * 2];
        }
        float s0 = q2.x * k0.x + q2.y * k0.y;
        float s1 = q2.x * k1.x + q2.y * k1.y;
        #pragma unroll
        for (int o = 16; o; o >>= 1) {
            s0 += __shfl_xor_sync(0xffffffffu, s0, o);
            s1 += __shfl_xor_sync(0xffffffffu, s1, o);
        }
        if (lane == 0) {
            s_sc[h][c] = s0 * 0.125f;
            if (has1) s_sc[h][c + 1] = s1 * 0.125f;
        }
    }
    __syncwarp();

    float mx = -3.0e38f;
    for (int c = lane; c < nc; c += 32) mx = fmaxf(mx, s_sc[h][c]);
    #pragma unroll
    for (int o = 16; o; o >>= 1) mx = fmaxf(mx, __shfl_xor_sync(0xffffffffu, mx, o));
    float l = 0.f;
    for (int c = lane; c < nc; c += 32) {
        float p = __expf(s_sc[h][c] - mx);
        s_sc[h][c] = p;
        l += p;
    }
    #pragma unroll
    for (int o = 16; o; o >>= 1) l += __shfl_xor_sync(0xffffffffu, l, o);
    __syncwarp();

    float ax = 0.f, ay = 0.f;
    for (int c = 0; c < nc; c += 2) {
        float p0 = s_sc[h][c];
        float2 v0 = *(const float2*)&g_v[s_cand[c] * D + h * DHD + lane * 2];
        if (c + 1 < nc) {
            float p1 = s_sc[h][c + 1];
            float2 v1 = *(const float2*)&g_v[s_cand[c + 1] * D + h * DHD + lane * 2];
            ax += p0 * v0.x + p1 * v1.x;
            ay += p0 * v0.y + p1 * v1.y;
        } else {
            ax += p0 * v0.x;
            ay += p0 * v0.y;
        }
    }
    float inv = 1.f / l;
    float vx = ax * inv, vy = ay * inv;
    __nv_bfloat16 hx = __float2bfloat16(vx), hy = __float2bfloat16(vy);
    __nv_bfloat16 lx = __float2bfloat16(vx - __bfloat162float(hx));
    __nv_bfloat16 ly = __float2bfloat16(vy - __bfloat162float(hy));
    *(__nv_bfloat162*)&g_aohi[base + lane * 2] = __nv_bfloat162(hx, hy);
    *(__nv_bfloat162*)&g_aolo[base + lane * 2] = __nv_bfloat162(lx, ly);
}

// ================= classifier =================
__global__ void k_cls(const float* __restrict__ W2, const float* __restrict__ b2,
                      float* __restrict__ out) {
    int warp = (blockIdx.x * blockDim.x + threadIdx.x) >> 5;
    int lane = threadIdx.x & 31;
    if (warp >= NE) return;
    float x[8];
    #pragma unroll
    for (int i = 0; i < 8; ++i) {
        size_t id = (size_t)warp * D + lane + i * 32;
        x[i] = __bfloat162float(g_hidhi[id]) + __bfloat162float(g_hidlo[id]);
    }
    float res = 0.f;
    #pragma unroll
    for (int c = 0; c < CLS; ++c) {
        float s = 0.f;
        #pragma unroll
        for (int i = 0; i < 8; ++i) s += x[i] * W2[(size_t)(lane + i * 32) * CLS + c];
        #pragma unroll
        for (int o = 16; o; o >>= 1) s += __shfl_xor_sync(0xffffffffu, s, o);
        if (lane == c) res = s + b2[c];
    }
    if (lane < CLS) out[(size_t)warp * CLS + lane] = res;
}

// ================= host =================
extern "C" void kernel_launch(void* const* d_in, const int* in_sizes, int n_in,
                              void* d_out, int out_size) {
    const float* nf   = (const float*)d_in[0];
    const float* efi  = (const float*)d_in[1];
    const int*   ei   = (const int*)d_in[2];
    const float* Wn_r = (const float*)d_in[3];
    const float* bn_r = (const float*)d_in[4];
    const float* We_r = (const float*)d_in[5];
    const float* be_r = (const float*)d_in[6];
    const float* Wnp  = (const float*)d_in[7];
    const float* bnp  = (const float*)d_in[8];
    const float* Wq   = (const float*)d_in[9];
    const float* bq   = (const float*)d_in[10];
    const float* Wk   = (const float*)d_in[11];
    const float* bk   = (const float*)d_in[12];
    const float* Wv   = (const float*)d_in[13];
    const float* bv   = (const float*)d_in[14];
    const float* Wo   = (const float*)d_in[15];
    const float* bo   = (const float*)d_in[16];
    const float* W1   = (const float*)d_in[17];
    const float* b1   = (const float*)d_in[18];
    const float* W2   = (const float*)d_in[19];
    const float* b2   = (const float*)d_in[20];
    float* out = (float*)d_out;

    cudaFuncSetAttribute(k_gemm_h, cudaFuncAttributeMaxDynamicSharedMemorySize, F_BYTES);
    cudaFuncSetAttribute(k_gemm_qkv, cudaFuncAttributeMaxDynamicSharedMemorySize, F_BYTES);
    cudaFuncSetAttribute(k_gemm_sp<0, 1, 2>, cudaFuncAttributeMaxDynamicSharedMemorySize, F_BYTES);
    cudaFuncSetAttribute(k_gemm_sp<1, 2, 3>, cudaFuncAttributeMaxDynamicSharedMemorySize, F_BYTES);

    k_front<<<752, 256>>>(nf, efi, ei, Wn_r, bn_r, We_r, be_r, Wnp, Wq, Wk, Wv, Wo, W1);
    k_build<<<3, 1024>>>();

    dim3 gg(D / 64, NE / 128);      // (4, 32) = 128 CTAs: one wave
    k_gemm_h<<<gg, GT, F_BYTES>>>(nf, efi, bnp);             // h (split)
    k_gemm_qkv<<<gg, GT, F_BYTES>>>(bq, bk, bv);             // q,k,v fp32
    k_attn<<<NE, 128>>>();                                   // ao (split)
    k_gemm_sp<0, 1, 2><<<gg, GT, F_BYTES>>>(4, bo);          // o (split)
    k_gemm_sp<1, 2, 3><<<gg, GT, F_BYTES>>>(5, b1);          // hid (split)
    k_cls<<<(NE * 32 + 255) / 256, 256>>>(W2, b2, out);
}

// round 15
// speedup vs baseline: 1.0368x; 1.0346x over previous
#include <cuda_runtime.h>
#include <cuda_bf16.h>
#include <cuda_fp16.h>
#include <math.h>
#include <stdint.h>

#define NN    1024
#define NE    4096
#define D     256
#define HN    4
#define DHD   64
#define NODEK 512
#define EDGEK 2048
#define CLS   16
#define MAXC  1024

// full-K resident GEMM: CTA 128x64 tile, K=256, 16 warps (8m x 2n), warp 16x32
#define FAPITCH 264
#define F_AHI 0
#define F_ALO (128 * FAPITCH)
#define F_BHI (2 * 128 * FAPITCH)
#define F_BLO (2 * 128 * FAPITCH + 64 * FAPITCH)
#define F_ELEMS (2 * 128 * FAPITCH + 2 * 64 * FAPITCH)
#define F_BYTES (F_ELEMS * 2)   // 202752 B -> 1 CTA/SM; grid 128 <= 148: one wave
#define GT 512                  // GEMM CTA threads (16 warps)

// ---------------- scratch ----------------
__device__ float g_nscore[NN];
__device__ float g_escore[NE];
__device__ int   g_nmask[NN];
__device__ int   g_emask[NE];
__device__ int   g_src[NE], g_dst[NE];
__device__ int   g_off[NN + 1];
__device__ int   g_inc[2 * NE];
__device__ float g_q[NE * D];
__device__ float g_k[NE * D];
__device__ float g_v[NE * D];
// split activations: h in bf16 (feeds 3-term bf16 qkv), ao/o/hid in fp16 (2-term path)
__device__ __nv_bfloat16 g_hhi[NE * D], g_hlo[NE * D];
__device__ __half g_aohi[NE * D], g_aolo[NE * D];
__device__ __half g_ohi[NE * D],  g_olo[NE * D];
__device__ __half g_hidhi[NE * D], g_hidlo[NE * D];
// transposed split weights: [w][n][k]; slots 0-3 bf16 hi/lo, slots 4-5 fp16 hi/lo
__device__ __nv_bfloat16 g_wthi[6 * D * D];
__device__ __nv_bfloat16 g_wtlo[6 * D * D];

// ================= 1: fused front-end =================
__global__ void k_front(const float* __restrict__ nf, const float* __restrict__ efi,
                        const int* __restrict__ ei,
                        const float* __restrict__ Wn, const float* __restrict__ bn,
                        const float* __restrict__ We, const float* __restrict__ be,
                        const float* __restrict__ Wnp, const float* __restrict__ Wq,
                        const float* __restrict__ Wk, const float* __restrict__ Wv,
                        const float* __restrict__ Wo, const float* __restrict__ W1) {
    int b = blockIdx.x;
    int tid = threadIdx.x;
    if (b < 96) {
        __shared__ float s[64][65];
        int w = b >> 4, t16 = b & 15;
        const float* W;
        switch (w) {
            case 0: W = Wnp; break;
            case 1: W = Wq; break;
            case 2: W = Wk; break;
            case 3: W = Wv; break;
            case 4: W = Wo; break;
            default: W = W1; break;
        }
        int n0 = (t16 & 3) * 64, k0 = (t16 >> 2) * 64;
        int n4 = (tid & 15) * 4, kr = tid >> 4;
        #pragma unroll
        for (int kk = kr; kk < 64; kk += 16) {
            float4 v = *(const float4*)&W[(size_t)(k0 + kk) * D + n0 + n4];
            s[kk][n4] = v.x;
            s[kk][n4 + 1] = v.y;
            s[kk][n4 + 2] = v.z;
            s[kk][n4 + 3] = v.w;
        }
        __syncthreads();
        int nl = tid >> 2, kq = (tid & 3) * 16;
        unsigned short hi[16], lo[16];
        #pragma unroll
        for (int i = 0; i < 16; ++i) {
            float x = s[kq + i][nl];
            if (w < 4) {  // bf16 split (3-term path)
                __nv_bfloat16 h = __float2bfloat16(x);
                __nv_bfloat16 l = __float2bfloat16(x - __bfloat162float(h));
                hi[i] = *(unsigned short*)&h;
                lo[i] = *(unsigned short*)&l;
            } else {      // fp16 split (2-term path: only hi is consumed)
                __half h = __float2half(x);
                __half l = __float2half(x - __half2float(h));
                hi[i] = *(unsigned short*)&h;
                lo[i] = *(unsigned short*)&l;
            }
        }
        size_t off = (size_t)w * D * D + (size_t)(n0 + nl) * D + k0 + kq;
        unsigned short* WH = (unsigned short*)g_wthi;
        unsigned short* WL = (unsigned short*)g_wtlo;
        *(uint4*)&WH[off] = *(uint4*)&hi[0];
        *(uint4*)&WH[off + 8] = *(uint4*)&hi[8];
        *(uint4*)&WL[off] = *(uint4*)&lo[0];
        *(uint4*)&WL[off + 8] = *(uint4*)&lo[8];
    } else if (b < 112) {
        __shared__ int sh[256];
        int acc = 0;
        for (int i = tid; i < 2048; i += 256) acc |= ei[2 * i + 1];
        sh[tid] = acc;
        __syncthreads();
        for (int s2 = 128; s2 > 0; s2 >>= 1) {
            if (tid < s2) sh[tid] |= sh[tid + s2];
            __syncthreads();
        }
        int is64 = (sh[0] == 0) ? 1 : 0;
        int i = (b - 96) * 256 + tid;
        int s, d;
        if (is64) { s = ei[2 * i]; d = ei[2 * (NE + i)]; }
        else      { s = ei[i];     d = ei[NE + i]; }
        g_src[i] = s;
        g_dst[i] = d;
    } else {
        int warp = (b - 112) * 8 + (tid >> 5);
        int lane = tid & 31;
        const float* x;
        const float* w;
        if (warp < NN) { x = nf + (size_t)warp * D; w = Wn; }
        else           { x = efi + (size_t)(warp - NN) * D; w = We; }
        float s = 0.f;
        #pragma unroll
        for (int i = 0; i < D / 32; ++i) s += x[lane + i * 32] * w[lane + i * 32];
        #pragma unroll
        for (int o = 16; o; o >>= 1) s += __shfl_xor_sync(0xffffffffu, s, o);
        if (lane == 0) {
            if (warp < NN) g_nscore[warp] = s + bn[0];
            else           g_escore[warp - NN] = s + be[0];
        }
    }
}

// ================= 2: fused build =================
struct TkSmem {
    unsigned su[NE];
    int hist[256];
    unsigned pref;
    int krem;
    int wagg[32];
};
struct IncSmem {
    int cnt[NN];
    int off[NN];
    int pos[NN];
    int inc[2 * NE];
};
union BuildSmem {
    TkSmem tk;
    IncSmem in;
};

__global__ void __launch_bounds__(1024, 1) k_build() {
    __shared__ BuildSmem sm;
    int tid = threadIdx.x;
    int lane = tid & 31, wid = tid >> 5;

    if (blockIdx.x < 2) {
        const bool is_edge = (blockIdx.x == 1);
        const float* sc = is_edge ? g_escore : g_nscore;
        int* mask = is_edge ? g_emask : g_nmask;
        const int n = is_edge ? NE : NN;
        const int kk = is_edge ? EDGEK : NODEK;
        int items = n >> 10;

        for (int j = 0; j < items; ++j) {
            int i = tid * items + j;
            unsigned bb = __float_as_uint(sc[i]);
            sm.tk.su[i] = (bb & 0x80000000u) ? ~bb : (bb | 0x80000000u);
        }
        if (tid == 0) { sm.tk.pref = 0u; sm.tk.krem = kk; }
        __syncthreads();

        for (int shift = 24; shift >= 0; shift -= 8) {
            unsigned prefix = sm.tk.pref;
            unsigned done_mask = (shift == 24) ? 0u : (0xFFFFFFFFu << (shift + 8));
            if (tid < 256) sm.tk.hist[tid] = 0;
            __syncthreads();
            for (int j = 0; j < items; ++j) {
                unsigned u = sm.tk.su[tid * items + j];
                if ((u & done_mask) == prefix)
                    atomicAdd(&sm.tk.hist[(u >> shift) & 255], 1);
            }
            __syncthreads();
            if (wid == 0) {
                int krem = sm.tk.krem;
                int gsum = 0;
                #pragma unroll
                for (int c = 0; c < 8; ++c) gsum += sm.tk.hist[lane * 8 + c];
                int x = gsum;
                #pragma unroll
                for (int off = 1; off < 32; off <<= 1) {
                    int t = __shfl_down_sync(0xffffffffu, x, off);
                    if (lane + off < 32) x += t;
                }
                int above = x - gsum;
                bool hit = (above < krem) && (x >= krem);
                unsigned bal = __ballot_sync(0xffffffffu, hit);
                int srcl = __ffs(bal) - 1;
                if (lane == srcl) {
                    int cum = above;
                    #pragma unroll
                    for (int c = 7; c >= 0; --c) {
                        int bb = lane * 8 + c;
                        int hc = sm.tk.hist[bb];
                        if (cum + hc >= krem) {
                            sm.tk.pref = prefix | ((unsigned)bb << shift);
                            sm.tk.krem = krem - cum;
                            break;
                        }
                        cum += hc;
                    }
                }
            }
            __syncthreads();
        }
        unsigned T = sm.tk.pref;
        int r = sm.tk.krem;

        int ct = 0;
        for (int j = 0; j < items; ++j) ct += (sm.tk.su[tid * items + j] == T) ? 1 : 0;
        int scan = ct;
        #pragma unroll
        for (int off = 1; off < 32; off <<= 1) {
            int t = __shfl_up_sync(0xffffffffu, scan, off);
            if (lane >= off) scan += t;
        }
        if (lane == 31) sm.tk.wagg[wid] = scan;
        __syncthreads();
        if (wid == 0) {
            int v = sm.tk.wagg[lane];
            #pragma unroll
            for (int off = 1; off < 32; off <<= 1) {
                int t = __shfl_up_sync(0xffffffffu, v, off);
                if (lane >= off) v += t;
            }
            sm.tk.wagg[lane] = v;
        }
        __syncthreads();
        int excl = (wid > 0 ? sm.tk.wagg[wid - 1] : 0) + scan - ct;

        for (int j = 0; j < items; ++j) {
            int i = tid * items + j;
            unsigned u = sm.tk.su[i];
            int mk;
            if (u > T) mk = 1;
            else if (u == T) { mk = (excl < r) ? 1 : 0; excl++; }
            else mk = 0;
            mask[i] = mk;
        }
    } else {
        sm.in.cnt[tid] = 0;
        __syncthreads();
        #pragma unroll
        for (int j = 0; j < 4; ++j) {
            int e = j * 1024 + tid;
            int a = g_src[e], b = g_dst[e];
            atomicAdd(&sm.in.cnt[a], 1);
            if (b != a) atomicAdd(&sm.in.cnt[b], 1);
        }
        __syncthreads();
        int own = sm.in.cnt[tid];
        int val = own;
        for (int dd = 1; dd < 1024; dd <<= 1) {
            int t = (tid >= dd) ? sm.in.cnt[tid - dd] : 0;
            __syncthreads();
            val += t;
            sm.in.cnt[tid] = val;
            __syncthreads();
        }
        int offv = val - own;
        sm.in.off[tid] = offv;
        sm.in.pos[tid] = offv;
        if (tid == 1023) g_off[1024] = val;
        g_off[tid] = offv;
        __syncthreads();
        int total = sm.in.cnt[1023];
        #pragma unroll
        for (int j = 0; j < 4; ++j) {
            int e = j * 1024 + tid;
            int a = g_src[e], b = g_dst[e];
            sm.in.inc[atomicAdd(&sm.in.pos[a], 1)] = e;
            if (b != a) sm.in.inc[atomicAdd(&sm.in.pos[b], 1)] = e;
        }
        __syncthreads();
        {
            int s = sm.in.off[tid];
            int t = sm.in.pos[tid];
            for (int i = s + 1; i < t; ++i) {
                int v = sm.in.inc[i];
                int j = i - 1;
                while (j >= s && sm.in.inc[j] > v) { sm.in.inc[j + 1] = sm.in.inc[j]; --j; }
                sm.in.inc[j + 1] = v;
            }
        }
        __syncthreads();
        for (int i = tid; i < total; i += 1024) g_inc[i] = sm.in.inc[i];
    }
}

// ================= GEMM primitives =================
__device__ __forceinline__ void mma_bf16(float* c, const uint32_t* a, const uint32_t* b) {
    asm volatile(
        "mma.sync.aligned.m16n8k16.row.col.f32.bf16.bf16.f32 "
        "{%0,%1,%2,%3}, {%4,%5,%6,%7}, {%8,%9}, {%0,%1,%2,%3};"
        : "+f"(c[0]), "+f"(c[1]), "+f"(c[2]), "+f"(c[3])
        : "r"(a[0]), "r"(a[1]), "r"(a[2]), "r"(a[3]), "r"(b[0]), "r"(b[1]));
}
__device__ __forceinline__ void mma_f16(float* c, const uint32_t* a, const uint32_t* b) {
    asm volatile(
        "mma.sync.aligned.m16n8k16.row.col.f32.f16.f16.f32 "
        "{%0,%1,%2,%3}, {%4,%5,%6,%7}, {%8,%9}, {%0,%1,%2,%3};"
        : "+f"(c[0]), "+f"(c[1]), "+f"(c[2]), "+f"(c[3])
        : "r"(a[0]), "r"(a[1]), "r"(a[2]), "r"(a[3]), "r"(b[0]), "r"(b[1]));
}

__device__ __forceinline__ void ldm_x4(uint32_t* r, uint32_t addr) {
    asm volatile("ldmatrix.sync.aligned.m8n8.x4.shared.b16 {%0,%1,%2,%3}, [%4];"
                 : "=r"(r[0]), "=r"(r[1]), "=r"(r[2]), "=r"(r[3]) : "r"(addr));
}

__device__ __forceinline__ void cp16(uint32_t s, const void* g) {
    asm volatile("cp.async.cg.shared.global [%0], [%1], 16;" :: "r"(s), "l"(g));
}
__device__ __forceinline__ void cp_commit() {
    asm volatile("cp.async.commit_group;" ::: "memory");
}
__device__ __forceinline__ void cp_wait0() {
    asm volatile("cp.async.wait_group 0;" ::: "memory");
}
__device__ __forceinline__ void cp_wait1() {
    asm volatile("cp.async.wait_group 1;" ::: "memory");
}

__device__ __forceinline__ void split_store_a(__nv_bfloat16* as_hi, __nv_bfloat16* as_lo,
                                              int o, float4 a) {
    __nv_bfloat16 h0 = __float2bfloat16(a.x), h1 = __float2bfloat16(a.y);
    __nv_bfloat16 h2 = __float2bfloat16(a.z), h3 = __float2bfloat16(a.w);
    __nv_bfloat16 l0 = __float2bfloat16(a.x - __bfloat162float(h0));
    __nv_bfloat16 l1 = __float2bfloat16(a.y - __bfloat162float(h1));
    __nv_bfloat16 l2 = __float2bfloat16(a.z - __bfloat162float(h2));
    __nv_bfloat16 l3 = __float2bfloat16(a.w - __bfloat162float(h3));
    *(__nv_bfloat162*)&as_hi[o]     = __nv_bfloat162(h0, h1);
    *(__nv_bfloat162*)&as_hi[o + 2] = __nv_bfloat162(h2, h3);
    *(__nv_bfloat162*)&as_lo[o]     = __nv_bfloat162(l0, l1);
    *(__nv_bfloat162*)&as_lo[o + 2] = __nv_bfloat162(l2, l3);
}

// async copy A half [128 x 128] (hi+lo): kh selects k in [kh*128, kh*128+128)
template <typename T>
__device__ __forceinline__ void cp_a_half(uint32_t ah_u, uint32_t al_u,
                                          const T* Ahi, const T* Alo,
                                          int m0, int tid, int kh) {
    int kb = kh * 128;
    #pragma unroll
    for (int it = 0; it < 4; ++it) {
        int idx = it * GT + tid;
        int m = idx >> 4, kq = kb + (idx & 15) * 8;
        uint32_t so = (uint32_t)((m * FAPITCH + kq) * 2);
        cp16(ah_u + so, &Ahi[(size_t)(m0 + m) * D + kq]);
        cp16(al_u + so, &Alo[(size_t)(m0 + m) * D + kq]);
    }
}

// async copy B [64 x 256] hi+lo (bf16 3-term path)
__device__ __forceinline__ void cp_b_full(uint32_t bh_u, uint32_t bl_u,
                                          int wslot, int n0, int tid) {
    const __nv_bfloat16* Bh = g_wthi + (size_t)wslot * D * D;
    const __nv_bfloat16* Bl = g_wtlo + (size_t)wslot * D * D;
    #pragma unroll
    for (int it = 0; it < 4; ++it) {
        int idx = it * GT + tid;
        int n = idx >> 5, kq = (idx & 31) * 8;
        uint32_t so = (uint32_t)((n * FAPITCH + kq) * 2);
        cp16(bh_u + so, &Bh[(size_t)(n0 + n) * D + kq]);
        cp16(bl_u + so, &Bl[(size_t)(n0 + n) * D + kq]);
    }
}

// async copy B [64 x 256] hi only (fp16 2-term path)
__device__ __forceinline__ void cp_b_hi(uint32_t bh_u, int wslot, int n0, int tid) {
    const unsigned short* Bh = (const unsigned short*)g_wthi + (size_t)wslot * D * D;
    #pragma unroll
    for (int it = 0; it < 2; ++it) {
        int idx = it * GT + tid;
        int n = idx >> 4, kq = (idx & 15) * 16;
        uint32_t so = (uint32_t)((n * FAPITCH + kq) * 2);
        cp16(bh_u + so, &Bh[(size_t)(n0 + n) * D + kq]);
        cp16(bh_u + so + 16, &Bh[(size_t)(n0 + n) * D + kq + 8]);
    }
}

// ---- 3-term bf16 inner loop (16-warp layout, warp 16x32) ----
__device__ __forceinline__ void ld_frags6(uint32_t ah_u, uint32_t al_u,
                                          uint32_t bh_u, uint32_t bl_u,
                                          uint32_t aoff, uint32_t boff0, uint32_t boff1,
                                          uint32_t kb2, uint32_t f[6][4]) {
    ldm_x4(f[0], ah_u + aoff + kb2);
    ldm_x4(f[1], al_u + aoff + kb2);
    ldm_x4(f[2], bh_u + boff0 + kb2);
    ldm_x4(f[3], bh_u + boff1 + kb2);
    ldm_x4(f[4], bl_u + boff0 + kb2);
    ldm_x4(f[5], bl_u + boff1 + kb2);
}

__device__ __forceinline__ void issue_mmas6(uint32_t f[6][4], float acc[4][4]) {
    #pragma unroll
    for (int nf = 0; nf < 4; ++nf)
        mma_bf16(acc[nf], f[0], &f[2 + (nf >> 1)][(nf & 1) * 2]);   // hi*hi
    #pragma unroll
    for (int nf = 0; nf < 4; ++nf)
        mma_bf16(acc[nf], f[0], &f[4 + (nf >> 1)][(nf & 1) * 2]);   // hi*lo
    #pragma unroll
    for (int nf = 0; nf < 4; ++nf)
        mma_bf16(acc[nf], f[1], &f[2 + (nf >> 1)][(nf & 1) * 2]);   // lo*hi
}

__device__ __forceinline__ void mma_steps8(uint32_t ah_u, uint32_t al_u,
                                           uint32_t bh_u, uint32_t bl_u,
                                           int wm, int wn, int lane,
                                           int ks0, float acc[4][4]) {
    int a_row = wm * 16 + (lane & 15);
    int a_ko = (lane >> 4) << 3;
    uint32_t aoff = (uint32_t)((a_row * FAPITCH + a_ko) * 2);
    int b_row = wn * 32 + (lane & 7) + ((lane >> 4) << 3);
    int b_ko = ((lane >> 3) & 1) << 3;
    uint32_t boff0 = (uint32_t)((b_row * FAPITCH + b_ko) * 2);
    uint32_t boff1 = (uint32_t)(((b_row + 16) * FAPITCH + b_ko) * 2);

    uint32_t fr[2][6][4];
    ld_frags6(ah_u, al_u, bh_u, bl_u, aoff, boff0, boff1, (uint32_t)(ks0 * 32), fr[0]);
    #pragma unroll
    for (int s = 0; s < 8; ++s) {
        if (s < 7)
            ld_frags6(ah_u, al_u, bh_u, bl_u, aoff, boff0, boff1,
                      (uint32_t)((ks0 + s + 1) * 32), fr[(s + 1) & 1]);
        issue_mmas6(fr[s & 1], acc);
    }
}

// ---- 2-term fp16 inner loop: (Ahi+Alo)*Bhi ----
__device__ __forceinline__ void mma_steps8_f16(uint32_t ah_u, uint32_t al_u, uint32_t bh_u,
                                               int wm, int wn, int lane,
                                               int ks0, float acc[4][4]) {
    int a_row = wm * 16 + (lane & 15);
    int a_ko = (lane >> 4) << 3;
    uint32_t aoff = (uint32_t)((a_row * FAPITCH + a_ko) * 2);
    int b_row = wn * 32 + (lane & 7) + ((lane >> 4) << 3);
    int b_ko = ((lane >> 3) & 1) << 3;
    uint32_t boff0 = (uint32_t)((b_row * FAPITCH + b_ko) * 2);
    uint32_t boff1 = (uint32_t)(((b_row + 16) * FAPITCH + b_ko) * 2);

    uint32_t fr[2][4][4];
    {
        uint32_t kb2 = (uint32_t)(ks0 * 32);
        ldm_x4(fr[0][0], ah_u + aoff + kb2);
        ldm_x4(fr[0][1], al_u + aoff + kb2);
        ldm_x4(fr[0][2], bh_u + boff0 + kb2);
        ldm_x4(fr[0][3], bh_u + boff1 + kb2);
    }
    #pragma unroll
    for (int s = 0; s < 8; ++s) {
        if (s < 7) {
            uint32_t kb2 = (uint32_t)((ks0 + s + 1) * 32);
            int nb = (s + 1) & 1;
            ldm_x4(fr[nb][0], ah_u + aoff + kb2);
            ldm_x4(fr[nb][1], al_u + aoff + kb2);
            ldm_x4(fr[nb][2], bh_u + boff0 + kb2);
            ldm_x4(fr[nb][3], bh_u + boff1 + kb2);
        }
        uint32_t (*f)[4] = fr[s & 1];
        #pragma unroll
        for (int nf = 0; nf < 4; ++nf)
            mma_f16(acc[nf], f[0], &f[2 + (nf >> 1)][(nf & 1) * 2]);
        #pragma unroll
        for (int nf = 0; nf < 4; ++nf)
            mma_f16(acc[nf], f[1], &f[2 + (nf >> 1)][(nf & 1) * 2]);
    }
}

// ================= GEMM kernels (512 threads, 16 warps) =================
// h GEMM: A computed on the fly (nf[src]+nf[dst]); B loads async behind it
__global__ void __launch_bounds__(GT) k_gemm_h(const float* __restrict__ nf,
                                               const float* __restrict__ efi,
                                               const float* __restrict__ bias) {
    extern __shared__ __nv_bfloat16 smx[];
    __nv_bfloat16* as_hi = smx + F_AHI;
    __nv_bfloat16* as_lo = smx + F_ALO;
    uint32_t base = (uint32_t)__cvta_generic_to_shared(smx);
    uint32_t ah_u = base + F_AHI * 2, al_u = base + F_ALO * 2;
    uint32_t bh_u = base + F_BHI * 2, bl_u = base + F_BLO * 2;

    int tid = threadIdx.x;
    int wid = tid >> 5, lane = tid & 31;
    int g = lane >> 2, t = lane & 3;
    int wm = wid >> 1, wn = wid & 1;
    int m0 = blockIdx.y * 128, n0 = blockIdx.x * 64;

    cp_b_full(bh_u, bl_u, 0, n0, tid);
    cp_commit();
    #pragma unroll
    for (int it = 0; it < 16; ++it) {
        int idx = it * GT + tid;
        int m = idx >> 6, k4 = (idx & 63) * 4;
        int e = m0 + m;
        int a = g_src[e], b = g_dst[e];
        float4 xa = *(const float4*)&nf[(size_t)a * D + k4];
        float4 xb = *(const float4*)&nf[(size_t)b * D + k4];
        float4 s = {xa.x + xb.x, xa.y + xb.y, xa.z + xb.z, xa.w + xb.w};
        split_store_a(as_hi, as_lo, m * FAPITCH + k4, s);
    }
    cp_wait0();
    __syncthreads();

    float acc[4][4] = {};
    mma_steps8(ah_u, al_u, bh_u, bl_u, wm, wn, lane, 0, acc);
    mma_steps8(ah_u, al_u, bh_u, bl_u, wm, wn, lane, 8, acc);

    int r0 = m0 + wm * 16 + g;
    #pragma unroll
    for (int half = 0; half < 2; ++half) {
        int r = r0 + half * 8;
        int em = g_emask[r] & g_nmask[g_src[r]] & g_nmask[g_dst[r]];
        float fm = em ? 1.0f : 0.0f;
        #pragma unroll
        for (int nf2 = 0; nf2 < 4; ++nf2) {
            int c = n0 + wn * 32 + nf2 * 8 + 2 * t;
            float v0 = acc[nf2][half * 2 + 0] + bias[c] + fm * efi[(size_t)r * D + c];
            float v1 = acc[nf2][half * 2 + 1] + bias[c + 1] + fm * efi[(size_t)r * D + c + 1];
            __nv_bfloat16 h0 = __float2bfloat16(v0), h1 = __float2bfloat16(v1);
            __nv_bfloat16 l0 = __float2bfloat16(v0 - __bfloat162float(h0));
            __nv_bfloat16 l1 = __float2bfloat16(v1 - __bfloat162float(h1));
            *(__nv_bfloat162*)&g_hhi[(size_t)r * D + c] = __nv_bfloat162(h0, h1);
            *(__nv_bfloat162*)&g_hlo[(size_t)r * D + c] = __nv_bfloat162(l0, l1);
        }
    }
}

// fused q/k/v GEMM: A resident once; B(w+1) prefetch overlaps epilogue(w)
__global__ void __launch_bounds__(GT) k_gemm_qkv(
        const float* __restrict__ bq, const float* __restrict__ bk,
        const float* __restrict__ bv) {
    extern __shared__ __nv_bfloat16 smx[];
    uint32_t base = (uint32_t)__cvta_generic_to_shared(smx);
    uint32_t ah_u = base + F_AHI * 2, al_u = base + F_ALO * 2;
    uint32_t bh_u = base + F_BHI * 2, bl_u = base + F_BLO * 2;

    int tid = threadIdx.x;
    int wid = tid >> 5, lane = tid & 31;
    int g = lane >> 2, t = lane & 3;
    int wm = wid >> 1, wn = wid & 1;
    int m0 = blockIdx.y * 128, n0 = blockIdx.x * 64;

    cp_b_full(bh_u, bl_u, 1, n0, tid);
    cp_a_half(ah_u, al_u, g_hhi, g_hlo, m0, tid, 0);
    cp_commit();
    cp_a_half(ah_u, al_u, g_hhi, g_hlo, m0, tid, 1);
    cp_commit();

    #pragma unroll
    for (int w = 0; w < 3; ++w) {
        float acc[4][4] = {};
        if (w == 0) {
            cp_wait1();
            __syncthreads();
            mma_steps8(ah_u, al_u, bh_u, bl_u, wm, wn, lane, 0, acc);
            cp_wait0();
            __syncthreads();
            mma_steps8(ah_u, al_u, bh_u, bl_u, wm, wn, lane, 8, acc);
        } else {
            mma_steps8(ah_u, al_u, bh_u, bl_u, wm, wn, lane, 0, acc);
            mma_steps8(ah_u, al_u, bh_u, bl_u, wm, wn, lane, 8, acc);
        }

        if (w < 2) {
            __syncthreads();
            cp_b_full(bh_u, bl_u, 2 + w, n0, tid);
            cp_commit();
        }

        const float* bias = (w == 0) ? bq : (w == 1) ? bk : bv;
        float* C = (w == 0) ? g_q : (w == 1) ? g_k : g_v;
        int r0 = m0 + wm * 16 + g;
        #pragma unroll
        for (int nf = 0; nf < 4; ++nf) {
            int c = n0 + wn * 32 + nf * 8 + 2 * t;
            float bb0 = bias[c], bb1 = bias[c + 1];
            #pragma unroll
            for (int half = 0; half < 2; ++half) {
                int r = r0 + half * 8;
                float2 o2 = {acc[nf][half * 2 + 0] + bb0,
                             acc[nf][half * 2 + 1] + bb1};
                *(float2*)&C[(size_t)r * D + c] = o2;
            }
        }
        if (w < 2) {
            cp_wait0();
            __syncthreads();
        }
    }
}

// 2-term fp16 GEMM: STAGE 0: o = ao@Wo + bo; STAGE 1: hid = gelu(o@W1 + b1)
template <int STAGE>
__global__ void __launch_bounds__(GT) k_gemm_f16k(const float* __restrict__ bias) {
    extern __shared__ __nv_bfloat16 smx[];
    uint32_t base = (uint32_t)__cvta_generic_to_shared(smx);
    uint32_t ah_u = base + F_AHI * 2, al_u = base + F_ALO * 2;
    uint32_t bh_u = base + F_BHI * 2;

    const __half* Ahi = (STAGE == 0) ? g_aohi : g_ohi;
    const __half* Alo = (STAGE == 0) ? g_aolo : g_olo;
    __half* Chi = (STAGE == 0) ? g_ohi : g_hidhi;
    __half* Clo = (STAGE == 0) ? g_olo : g_hidlo;
    const int wslot = (STAGE == 0) ? 4 : 5;

    int tid = threadIdx.x;
    int wid = tid >> 5, lane = tid & 31;
    int g = lane >> 2, t = lane & 3;
    int wm = wid >> 1, wn = wid & 1;
    int m0 = blockIdx.y * 128, n0 = blockIdx.x * 64;

    cp_b_hi(bh_u, wslot, n0, tid);
    cp_a_half(ah_u, al_u, Ahi, Alo, m0, tid, 0);
    cp_commit();
    cp_a_half(ah_u, al_u, Ahi, Alo, m0, tid, 1);
    cp_commit();

    float acc[4][4] = {};
    cp_wait1();
    __syncthreads();
    mma_steps8_f16(ah_u, al_u, bh_u, wm, wn, lane, 0, acc);
    cp_wait0();
    __syncthreads();
    mma_steps8_f16(ah_u, al_u, bh_u, wm, wn, lane, 8, acc);

    int r0 = m0 + wm * 16 + g;
    #pragma unroll
    for (int nf = 0; nf < 4; ++nf) {
        int c = n0 + wn * 32 + nf * 8 + 2 * t;
        float bb0 = bias[c], bb1 = bias[c + 1];
        #pragma unroll
        for (int half = 0; half < 2; ++half) {
            int r = r0 + half * 8;
            float v0 = acc[nf][half * 2 + 0] + bb0;
            float v1 = acc[nf][half * 2 + 1] + bb1;
            if (STAGE == 1) {
                float x0 = v0, x1 = v1;
                float t0 = tanhf(0.7978845608028654f * (x0 + 0.044715f * x0 * x0 * x0));
                float t1 = tanhf(0.7978845608028654f * (x1 + 0.044715f * x1 * x1 * x1));
                v0 = 0.5f * x0 * (1.0f + t0);
                v1 = 0.5f * x1 * (1.0f + t1);
            }
            __half h0 = __float2half(v0), h1 = __float2half(v1);
            __half l0 = __float2half(v0 - __half2float(h0));
            __half l1 = __float2half(v1 - __half2float(h1));
            *(__half2*)&Chi[(size_t)r * D + c] = __halves2half2(h0, h1);
            *(__half2*)&Clo[(size_t)r * D + c] = __halves2half2(l0, l1);
        }
    }
}

// ================= sparse masked attention (2-way ILP) =================
__global__ void k_attn() {
    __shared__ int s_cand[MAXC];
    __shared__ float s_sc[HN][MAXC];
    __shared__ int s_n;
    int e = blockIdx.x;
    int tid = threadIdx.x;
    int h = tid >> 5, lane = tid & 31;
    int a = g_src[e], b = g_dst[e];
    int oa = g_off[a];
    int na = g_off[a + 1] - oa;

    for (int i = tid; i < na; i += 128) s_cand[i] = g_inc[oa + i];

    if (tid < 32) {
        int cnt = na;
        if (b != a) {
            int ob = g_off[b];
            int nb = g_off[b + 1] - ob;
            for (int i0 = 0; i0 < nb; i0 += 32) {
                int i = i0 + lane;
                int f = 0, keep = 0;
                if (i < nb) {
                    f = g_inc[ob + i];
                    keep = (g_src[f] != a && g_dst[f] != a) ? 1 : 0;
                }
                unsigned bal = __ballot_sync(0xffffffffu, keep != 0);
                if (keep) {
                    int pos = cnt + __popc(bal & ((1u << lane) - 1u));
                    if (pos < MAXC) s_cand[pos] = f;
                }
                cnt += __popc(bal);
            }
        }
        if (lane == 0) s_n = (cnt < MAXC) ? cnt : MAXC;
    }
    __syncthreads();
    int nc = s_n;
    int base = e * D + h * DHD;

    float2 q2 = *(const float2*)&g_q[base + lane * 2];

    for (int c = 0; c < nc; c += 2) {
        int f0 = s_cand[c];
        float2 k0 = *(const float2*)&g_k[f0 * D + h * DHD + lane * 2];
        bool has1 = (c + 1 < nc);
        float2 k1 = {0.f, 0.f};
        if (has1) {
            int f1 = s_cand[c + 1];
            k1 = *(const float2*)&g_k[f1 * D + h * DHD + lane * 2];
        }
        float s0 = q2.x * k0.x + q2.y * k0.y;
        float s1 = q2.x * k1.x + q2.y * k1.y;
        #pragma unroll
        for (int o = 16; o; o >>= 1) {
            s0 += __shfl_xor_sync(0xffffffffu, s0, o);
            s1 += __shfl_xor_sync(0xffffffffu, s1, o);
        }
        if (lane == 0) {
            s_sc[h][c] = s0 * 0.125f;
            if (has1) s_sc[h][c + 1] = s1 * 0.125f;
        }
    }
    __syncwarp();

    float mx = -3.0e38f;
    for (int c = lane; c < nc; c += 32) mx = fmaxf(mx, s_sc[h][c]);
    #pragma unroll
    for (int o = 16; o; o >>= 1) mx = fmaxf(mx, __shfl_xor_sync(0xffffffffu, mx, o));
    float l = 0.f;
    for (int c = lane; c < nc; c += 32) {
        float p = __expf(s_sc[h][c] - mx);
        s_sc[h][c] = p;
        l += p;
    }
    #pragma unroll
    for (int o = 16; o; o >>= 1) l += __shfl_xor_sync(0xffffffffu, l, o);
    __syncwarp();

    float ax = 0.f, ay = 0.f;
    for (int c = 0; c < nc; c += 2) {
        float p0 = s_sc[h][c];
        float2 v0 = *(const float2*)&g_v[s_cand[c] * D + h * DHD + lane * 2];
        if (c + 1 < nc) {
            float p1 = s_sc[h][c + 1];
            float2 v1 = *(const float2*)&g_v[s_cand[c + 1] * D + h * DHD + lane * 2];
            ax += p0 * v0.x + p1 * v1.x;
            ay += p0 * v0.y + p1 * v1.y;
        } else {
            ax += p0 * v0.x;
            ay += p0 * v0.y;
        }
    }
    float inv = 1.f / l;
    float vx = ax * inv, vy = ay * inv;
    __half hx = __float2half(vx), hy = __float2half(vy);
    __half lx = __float2half(vx - __half2float(hx));
    __half ly = __float2half(vy - __half2float(hy));
    *(__half2*)&g_aohi[base + lane * 2] = __halves2half2(hx, hy);
    *(__half2*)&g_aolo[base + lane * 2] = __halves2half2(lx, ly);
}

// ================= classifier =================
__global__ void k_cls(const float* __restrict__ W2, const float* __restrict__ b2,
                      float* __restrict__ out) {
    int warp = (blockIdx.x * blockDim.x + threadIdx.x) >> 5;
    int lane = threadIdx.x & 31;
    if (warp >= NE) return;
    float x[8];
    #pragma unroll
    for (int i = 0; i < 8; ++i) {
        size_t id = (size_t)warp * D + lane + i * 32;
        x[i] = __half2float(g_hidhi[id]) + __half2float(g_hidlo[id]);
    }
    float res = 0.f;
    #pragma unroll
    for (int c = 0; c < CLS; ++c) {
        float s = 0.f;
        #pragma unroll
        for (int i = 0; i < 8; ++i) s += x[i] * W2[(size_t)(lane + i * 32) * CLS + c];
        #pragma unroll
        for (int o = 16; o; o >>= 1) s += __shfl_xor_sync(0xffffffffu, s, o);
        if (lane == c) res = s + b2[c];
    }
    if (lane < CLS) out[(size_t)warp * CLS + lane] = res;
}

// ================= host =================
extern "C" void kernel_launch(void* const* d_in, const int* in_sizes, int n_in,
                              void* d_out, int out_size) {
    const float* nf   = (const float*)d_in[0];
    const float* efi  = (const float*)d_in[1];
    const int*   ei   = (const int*)d_in[2];
    const float* Wn_r = (const float*)d_in[3];
    const float* bn_r = (const float*)d_in[4];
    const float* We_r = (const float*)d_in[5];
    const float* be_r = (const float*)d_in[6];
    const float* Wnp  = (const float*)d_in[7];
    const float* bnp  = (const float*)d_in[8];
    const float* Wq   = (const float*)d_in[9];
    const float* bq   = (const float*)d_in[10];
    const float* Wk   = (const float*)d_in[11];
    const float* bk   = (const float*)d_in[12];
    const float* Wv   = (const float*)d_in[13];
    const float* bv   = (const float*)d_in[14];
    const float* Wo   = (const float*)d_in[15];
    const float* bo   = (const float*)d_in[16];
    const float* W1   = (const float*)d_in[17];
    const float* b1   = (const float*)d_in[18];
    const float* W2   = (const float*)d_in[19];
    const float* b2   = (const float*)d_in[20];
    float* out = (float*)d_out;

    cudaFuncSetAttribute(k_gemm_h, cudaFuncAttributeMaxDynamicSharedMemorySize, F_BYTES);
    cudaFuncSetAttribute(k_gemm_qkv, cudaFuncAttributeMaxDynamicSharedMemorySize, F_BYTES);
    cudaFuncSetAttribute(k_gemm_f16k<0>, cudaFuncAttributeMaxDynamicSharedMemorySize, F_BYTES);
    cudaFuncSetAttribute(k_gemm_f16k<1>, cudaFuncAttributeMaxDynamicSharedMemorySize, F_BYTES);

    k_front<<<752, 256>>>(nf, efi, ei, Wn_r, bn_r, We_r, be_r, Wnp, Wq, Wk, Wv, Wo, W1);
    k_build<<<3, 1024>>>();

    dim3 gg(D / 64, NE / 128);      // (4, 32) = 128 CTAs: one wave
    k_gemm_h<<<gg, GT, F_BYTES>>>(nf, efi, bnp);             // h (bf16 split)
    k_gemm_qkv<<<gg, GT, F_BYTES>>>(bq, bk, bv);             // q,k,v fp32 (3-term bf16)
    k_attn<<<NE, 128>>>();                                   // ao (fp16 split)
    k_gemm_f16k<0><<<gg, GT, F_BYTES>>>(bo);                 // o = ao@Wo (2-term fp16)
    k_gemm_f16k<1><<<gg, GT, F_BYTES>>>(b1);                 // hid = gelu(o@W1) (2-term fp16)
    k_cls<<<(NE * 32 + 255) / 256, 256>>>(W2, b2, out);
}

// round 16
// speedup vs baseline: 1.0713x; 1.0333x over previous
#include <cuda_runtime.h>
#include <cuda_bf16.h>
#include <cuda_fp16.h>
#include <math.h>
#include <stdint.h>

#define NN    1024
#define NE    4096
#define D     256
#define HN    4
#define DHD   64
#define NODEK 512
#define EDGEK 2048
#define CLS   16
#define MAXC  1024

// full-K resident GEMM: CTA 128x64 tile, K=256, 16 warps (8m x 2n), warp 16x32
#define FAPITCH 264
#define F_AHI 0
#define F_ALO (128 * FAPITCH)
#define F_BHI (2 * 128 * FAPITCH)
#define F_BLO (2 * 128 * FAPITCH + 64 * FAPITCH)
#define F_ELEMS (2 * 128 * FAPITCH + 2 * 64 * FAPITCH)
#define F_BYTES (F_ELEMS * 2)   // 202752 B -> 1 CTA/SM
#define GT 512                  // GEMM CTA threads (16 warps)

// ---------------- scratch ----------------
__device__ int   g_done;
__device__ float g_nscore[NN];
__device__ float g_escore[NE];
__device__ int   g_nmask[NN];
__device__ int   g_emask[NE];
__device__ int   g_src[NE], g_dst[NE];
__device__ int   g_off[NN + 1];
__device__ int   g_inc[2 * NE];
__device__ float g_q[NE * D];
__device__ float g_k[NE * D];
__device__ float g_v[NE * D];
// split activations: h in bf16 (3-term qkv), ao/o/hid in fp16 (2-term path)
__device__ __nv_bfloat16 g_hhi[NE * D], g_hlo[NE * D];
__device__ __half g_aohi[NE * D], g_aolo[NE * D];
__device__ __half g_ohi[NE * D],  g_olo[NE * D];
__device__ __half g_hidhi[NE * D], g_hidlo[NE * D];
// transposed split weights: [w][n][k]; slots 0-3 bf16 hi/lo, slots 4-5 fp16 hi/lo
__device__ __nv_bfloat16 g_wthi[6 * D * D];
__device__ __nv_bfloat16 g_wtlo[6 * D * D];

// ================= build smem layouts (live in dynamic smem of fused kernel) =================
struct TkSmem {
    unsigned su[NE];
    int hist[256];
    unsigned pref;
    int krem;
    int wagg[32];
};
struct IncSmem {
    int cnt[NN];
    int off[NN];
    int pos[NN];
    int inc[2 * NE];
};

// ================= 1: fused front-end =================
__global__ void k_front(const float* __restrict__ nf, const float* __restrict__ efi,
                        const int* __restrict__ ei,
                        const float* __restrict__ Wn, const float* __restrict__ bn,
                        const float* __restrict__ We, const float* __restrict__ be,
                        const float* __restrict__ Wnp, const float* __restrict__ Wq,
                        const float* __restrict__ Wk, const float* __restrict__ Wv,
                        const float* __restrict__ Wo, const float* __restrict__ W1) {
    int b = blockIdx.x;
    int tid = threadIdx.x;
    if (b == 0 && tid == 0) g_done = 0;   // reset flag for the fused h+build kernel
    if (b < 96) {
        __shared__ float s[64][65];
        int w = b >> 4, t16 = b & 15;
        const float* W;
        switch (w) {
            case 0: W = Wnp; break;
            case 1: W = Wq; break;
            case 2: W = Wk; break;
            case 3: W = Wv; break;
            case 4: W = Wo; break;
            default: W = W1; break;
        }
        int n0 = (t16 & 3) * 64, k0 = (t16 >> 2) * 64;
        int n4 = (tid & 15) * 4, kr = tid >> 4;
        #pragma unroll
        for (int kk = kr; kk < 64; kk += 16) {
            float4 v = *(const float4*)&W[(size_t)(k0 + kk) * D + n0 + n4];
            s[kk][n4] = v.x;
            s[kk][n4 + 1] = v.y;
            s[kk][n4 + 2] = v.z;
            s[kk][n4 + 3] = v.w;
        }
        __syncthreads();
        int nl = tid >> 2, kq = (tid & 3) * 16;
        unsigned short hi[16], lo[16];
        #pragma unroll
        for (int i = 0; i < 16; ++i) {
            float x = s[kq + i][nl];
            if (w < 4) {
                __nv_bfloat16 h = __float2bfloat16(x);
                __nv_bfloat16 l = __float2bfloat16(x - __bfloat162float(h));
                hi[i] = *(unsigned short*)&h;
                lo[i] = *(unsigned short*)&l;
            } else {
                __half h = __float2half(x);
                __half l = __float2half(x - __half2float(h));
                hi[i] = *(unsigned short*)&h;
                lo[i] = *(unsigned short*)&l;
            }
        }
        size_t off = (size_t)w * D * D + (size_t)(n0 + nl) * D + k0 + kq;
        unsigned short* WH = (unsigned short*)g_wthi;
        unsigned short* WL = (unsigned short*)g_wtlo;
        *(uint4*)&WH[off] = *(uint4*)&hi[0];
        *(uint4*)&WH[off + 8] = *(uint4*)&hi[8];
        *(uint4*)&WL[off] = *(uint4*)&lo[0];
        *(uint4*)&WL[off + 8] = *(uint4*)&lo[8];
    } else if (b < 112) {
        __shared__ int sh[256];
        int acc = 0;
        for (int i = tid; i < 2048; i += 256) acc |= ei[2 * i + 1];
        sh[tid] = acc;
        __syncthreads();
        for (int s2 = 128; s2 > 0; s2 >>= 1) {
            if (tid < s2) sh[tid] |= sh[tid + s2];
            __syncthreads();
        }
        int is64 = (sh[0] == 0) ? 1 : 0;
        int i = (b - 96) * 256 + tid;
        int s, d;
        if (is64) { s = ei[2 * i]; d = ei[2 * (NE + i)]; }
        else      { s = ei[i];     d = ei[NE + i]; }
        g_src[i] = s;
        g_dst[i] = d;
    } else {
        int warp = (b - 112) * 8 + (tid >> 5);
        int lane = tid & 31;
        const float* x;
        const float* w;
        if (warp < NN) { x = nf + (size_t)warp * D; w = Wn; }
        else           { x = efi + (size_t)(warp - NN) * D; w = We; }
        float s = 0.f;
        #pragma unroll
        for (int i = 0; i < D / 32; ++i) s += x[lane + i * 32] * w[lane + i * 32];
        #pragma unroll
        for (int o = 16; o; o >>= 1) s += __shfl_xor_sync(0xffffffffu, s, o);
        if (lane == 0) {
            if (warp < NN) g_nscore[warp] = s + bn[0];
            else           g_escore[warp - NN] = s + be[0];
        }
    }
}

// ================= build bodies (512 threads) =================
__device__ void build_topk(TkSmem& tk, int role) {
    int tid = threadIdx.x;
    int lane = tid & 31, wid = tid >> 5;
    const bool is_edge = (role == 1);
    const float* sc = is_edge ? g_escore : g_nscore;
    int* mask = is_edge ? g_emask : g_nmask;
    const int n = is_edge ? NE : NN;
    const int kk = is_edge ? EDGEK : NODEK;
    int items = n >> 9;  // 2 or 8

    for (int j = 0; j < items; ++j) {
        int i = tid * items + j;
        unsigned bb = __float_as_uint(sc[i]);
        tk.su[i] = (bb & 0x80000000u) ? ~bb : (bb | 0x80000000u);
    }
    if (tid == 0) { tk.pref = 0u; tk.krem = kk; }
    __syncthreads();

    for (int shift = 24; shift >= 0; shift -= 8) {
        unsigned prefix = tk.pref;
        unsigned done_mask = (shift == 24) ? 0u : (0xFFFFFFFFu << (shift + 8));
        if (tid < 256) tk.hist[tid] = 0;
        __syncthreads();
        for (int j = 0; j < items; ++j) {
            unsigned u = tk.su[tid * items + j];
            if ((u & done_mask) == prefix)
                atomicAdd(&tk.hist[(u >> shift) & 255], 1);
        }
        __syncthreads();
        if (wid == 0) {
            int krem = tk.krem;
            int gsum = 0;
            #pragma unroll
            for (int c = 0; c < 8; ++c) gsum += tk.hist[lane * 8 + c];
            int x = gsum;
            #pragma unroll
            for (int off = 1; off < 32; off <<= 1) {
                int t = __shfl_down_sync(0xffffffffu, x, off);
                if (lane + off < 32) x += t;
            }
            int above = x - gsum;
            bool hit = (above < krem) && (x >= krem);
            unsigned bal = __ballot_sync(0xffffffffu, hit);
            int srcl = __ffs(bal) - 1;
            if (lane == srcl) {
                int cum = above;
                #pragma unroll
                for (int c = 7; c >= 0; --c) {
                    int bb = lane * 8 + c;
                    int hc = tk.hist[bb];
                    if (cum + hc >= krem) {
                        tk.pref = prefix | ((unsigned)bb << shift);
                        tk.krem = krem - cum;
                        break;
                    }
                    cum += hc;
                }
            }
        }
        __syncthreads();
    }
    unsigned T = tk.pref;
    int r = tk.krem;

    int ct = 0;
    for (int j = 0; j < items; ++j) ct += (tk.su[tid * items + j] == T) ? 1 : 0;
    int scan = ct;
    #pragma unroll
    for (int off = 1; off < 32; off <<= 1) {
        int t = __shfl_up_sync(0xffffffffu, scan, off);
        if (lane >= off) scan += t;
    }
    if (lane == 31) tk.wagg[wid] = scan;
    __syncthreads();
    if (wid == 0) {
        int v = (lane < 16) ? tk.wagg[lane] : 0;
        #pragma unroll
        for (int off = 1; off < 32; off <<= 1) {
            int t = __shfl_up_sync(0xffffffffu, v, off);
            if (lane >= off) v += t;
        }
        if (lane < 16) tk.wagg[lane] = v;
    }
    __syncthreads();
    int excl = (wid > 0 ? tk.wagg[wid - 1] : 0) + scan - ct;

    for (int j = 0; j < items; ++j) {
        int i = tid * items + j;
        unsigned u = tk.su[i];
        int mk;
        if (u > T) mk = 1;
        else if (u == T) { mk = (excl < r) ? 1 : 0; excl++; }
        else mk = 0;
        mask[i] = mk;
    }
    // release: masks visible, then signal
    __threadfence();
    __syncthreads();
    if (tid == 0) atomicAdd(&g_done, 1);
}

__device__ void build_inc(IncSmem& in) {
    int tid = threadIdx.x;
    in.cnt[tid] = 0;
    in.cnt[tid + 512] = 0;
    __syncthreads();
    #pragma unroll
    for (int j = 0; j < 8; ++j) {
        int e = j * 512 + tid;
        int a = g_src[e], b = g_dst[e];
        atomicAdd(&in.cnt[a], 1);
        if (b != a) atomicAdd(&in.cnt[b], 1);
    }
    __syncthreads();
    int c0 = in.cnt[2 * tid], c1 = in.cnt[2 * tid + 1];
    in.off[tid] = c0 + c1;   // pair sums (off[0..511] as scratch)
    __syncthreads();
    int val = in.off[tid];
    for (int dd = 1; dd < 512; dd <<= 1) {
        int t = (tid >= dd) ? in.off[tid - dd] : 0;
        __syncthreads();
        val += t;
        in.off[tid] = val;
        __syncthreads();
    }
    int exclPair = val - (c0 + c1);
    __syncthreads();             // scan fully done before clobbering cnt/pos
    in.pos[2 * tid] = exclPair;
    in.pos[2 * tid + 1] = exclPair + c0;
    in.cnt[2 * tid] = exclPair;            // cnt now holds start offsets
    in.cnt[2 * tid + 1] = exclPair + c0;
    g_off[2 * tid] = exclPair;
    g_off[2 * tid + 1] = exclPair + c0;
    if (tid == 511) g_off[1024] = val;
    __syncthreads();
    int total = in.off[511];
    #pragma unroll
    for (int j = 0; j < 8; ++j) {
        int e = j * 512 + tid;
        int a = g_src[e], b = g_dst[e];
        in.inc[atomicAdd(&in.pos[a], 1)] = e;
        if (b != a) in.inc[atomicAdd(&in.pos[b], 1)] = e;
    }
    __syncthreads();
    #pragma unroll
    for (int q = 0; q < 2; ++q) {
        int node = q * 512 + tid;
        int s = in.cnt[node], t = in.pos[node];
        for (int i = s + 1; i < t; ++i) {
            int v = in.inc[i];
            int j = i - 1;
            while (j >= s && in.inc[j] > v) { in.inc[j + 1] = in.inc[j]; --j; }
            in.inc[j + 1] = v;
        }
    }
    __syncthreads();
    for (int i = tid; i < total; i += 512) g_inc[i] = in.inc[i];
}

// ================= GEMM primitives =================
__device__ __forceinline__ void mma_bf16(float* c, const uint32_t* a, const uint32_t* b) {
    asm volatile(
        "mma.sync.aligned.m16n8k16.row.col.f32.bf16.bf16.f32 "
        "{%0,%1,%2,%3}, {%4,%5,%6,%7}, {%8,%9}, {%0,%1,%2,%3};"
        : "+f"(c[0]), "+f"(c[1]), "+f"(c[2]), "+f"(c[3])
        : "r"(a[0]), "r"(a[1]), "r"(a[2]), "r"(a[3]), "r"(b[0]), "r"(b[1]));
}
__device__ __forceinline__ void mma_f16(float* c, const uint32_t* a, const uint32_t* b) {
    asm volatile(
        "mma.sync.aligned.m16n8k16.row.col.f32.f16.f16.f32 "
        "{%0,%1,%2,%3}, {%4,%5,%6,%7}, {%8,%9}, {%0,%1,%2,%3};"
        : "+f"(c[0]), "+f"(c[1]), "+f"(c[2]), "+f"(c[3])
        : "r"(a[0]), "r"(a[1]), "r"(a[2]), "r"(a[3]), "r"(b[0]), "r"(b[1]));
}

__device__ __forceinline__ void ldm_x4(uint32_t* r, uint32_t addr) {
    asm volatile("ldmatrix.sync.aligned.m8n8.x4.shared.b16 {%0,%1,%2,%3}, [%4];"
                 : "=r"(r[0]), "=r"(r[1]), "=r"(r[2]), "=r"(r[3]) : "r"(addr));
}

__device__ __forceinline__ void cp16(uint32_t s, const void* g) {
    asm volatile("cp.async.cg.shared.global [%0], [%1], 16;" :: "r"(s), "l"(g));
}
__device__ __forceinline__ void cp_commit() {
    asm volatile("cp.async.commit_group;" ::: "memory");
}
__device__ __forceinline__ void cp_wait0() {
    asm volatile("cp.async.wait_group 0;" ::: "memory");
}
__device__ __forceinline__ void cp_wait1() {
    asm volatile("cp.async.wait_group 1;" ::: "memory");
}

__device__ __forceinline__ void split_store_a(__nv_bfloat16* as_hi, __nv_bfloat16* as_lo,
                                              int o, float4 a) {
    __nv_bfloat16 h0 = __float2bfloat16(a.x), h1 = __float2bfloat16(a.y);
    __nv_bfloat16 h2 = __float2bfloat16(a.z), h3 = __float2bfloat16(a.w);
    __nv_bfloat16 l0 = __float2bfloat16(a.x - __bfloat162float(h0));
    __nv_bfloat16 l1 = __float2bfloat16(a.y - __bfloat162float(h1));
    __nv_bfloat16 l2 = __float2bfloat16(a.z - __bfloat162float(h2));
    __nv_bfloat16 l3 = __float2bfloat16(a.w - __bfloat162float(h3));
    *(__nv_bfloat162*)&as_hi[o]     = __nv_bfloat162(h0, h1);
    *(__nv_bfloat162*)&as_hi[o + 2] = __nv_bfloat162(h2, h3);
    *(__nv_bfloat162*)&as_lo[o]     = __nv_bfloat162(l0, l1);
    *(__nv_bfloat162*)&as_lo[o + 2] = __nv_bfloat162(l2, l3);
}

template <typename T>
__device__ __forceinline__ void cp_a_half(uint32_t ah_u, uint32_t al_u,
                                          const T* Ahi, const T* Alo,
                                          int m0, int tid, int kh) {
    int kb = kh * 128;
    #pragma unroll
    for (int it = 0; it < 4; ++it) {
        int idx = it * GT + tid;
        int m = idx >> 4, kq = kb + (idx & 15) * 8;
        uint32_t so = (uint32_t)((m * FAPITCH + kq) * 2);
        cp16(ah_u + so, &Ahi[(size_t)(m0 + m) * D + kq]);
        cp16(al_u + so, &Alo[(size_t)(m0 + m) * D + kq]);
    }
}

__device__ __forceinline__ void cp_b_full(uint32_t bh_u, uint32_t bl_u,
                                          int wslot, int n0, int tid) {
    const __nv_bfloat16* Bh = g_wthi + (size_t)wslot * D * D;
    const __nv_bfloat16* Bl = g_wtlo + (size_t)wslot * D * D;
    #pragma unroll
    for (int it = 0; it < 4; ++it) {
        int idx = it * GT + tid;
        int n = idx >> 5, kq = (idx & 31) * 8;
        uint32_t so = (uint32_t)((n * FAPITCH + kq) * 2);
        cp16(bh_u + so, &Bh[(size_t)(n0 + n) * D + kq]);
        cp16(bl_u + so, &Bl[(size_t)(n0 + n) * D + kq]);
    }
}

__device__ __forceinline__ void cp_b_hi(uint32_t bh_u, int wslot, int n0, int tid) {
    const unsigned short* Bh = (const unsigned short*)g_wthi + (size_t)wslot * D * D;
    #pragma unroll
    for (int it = 0; it < 2; ++it) {
        int idx = it * GT + tid;
        int n = idx >> 4, kq = (idx & 15) * 16;
        uint32_t so = (uint32_t)((n * FAPITCH + kq) * 2);
        cp16(bh_u + so, &Bh[(size_t)(n0 + n) * D + kq]);
        cp16(bh_u + so + 16, &Bh[(size_t)(n0 + n) * D + kq + 8]);
    }
}

// ---- 3-term bf16 inner loop (16-warp layout, warp 16x32) ----
__device__ __forceinline__ void ld_frags6(uint32_t ah_u, uint32_t al_u,
                                          uint32_t bh_u, uint32_t bl_u,
                                          uint32_t aoff, uint32_t boff0, uint32_t boff1,
                                          uint32_t kb2, uint32_t f[6][4]) {
    ldm_x4(f[0], ah_u + aoff + kb2);
    ldm_x4(f[1], al_u + aoff + kb2);
    ldm_x4(f[2], bh_u + boff0 + kb2);
    ldm_x4(f[3], bh_u + boff1 + kb2);
    ldm_x4(f[4], bl_u + boff0 + kb2);
    ldm_x4(f[5], bl_u + boff1 + kb2);
}

__device__ __forceinline__ void issue_mmas6(uint32_t f[6][4], float acc[4][4]) {
    #pragma unroll
    for (int nf = 0; nf < 4; ++nf)
        mma_bf16(acc[nf], f[0], &f[2 + (nf >> 1)][(nf & 1) * 2]);
    #pragma unroll
    for (int nf = 0; nf < 4; ++nf)
        mma_bf16(acc[nf], f[0], &f[4 + (nf >> 1)][(nf & 1) * 2]);
    #pragma unroll
    for (int nf = 0; nf < 4; ++nf)
        mma_bf16(acc[nf], f[1], &f[2 + (nf >> 1)][(nf & 1) * 2]);
}

__device__ __forceinline__ void mma_steps8(uint32_t ah_u, uint32_t al_u,
                                           uint32_t bh_u, uint32_t bl_u,
                                           int wm, int wn, int lane,
                                           int ks0, float acc[4][4]) {
    int a_row = wm * 16 + (lane & 15);
    int a_ko = (lane >> 4) << 3;
    uint32_t aoff = (uint32_t)((a_row * FAPITCH + a_ko) * 2);
    int b_row = wn * 32 + (lane & 7) + ((lane >> 4) << 3);
    int b_ko = ((lane >> 3) & 1) << 3;
    uint32_t boff0 = (uint32_t)((b_row * FAPITCH + b_ko) * 2);
    uint32_t boff1 = (uint32_t)(((b_row + 16) * FAPITCH + b_ko) * 2);

    uint32_t fr[2][6][4];
    ld_frags6(ah_u, al_u, bh_u, bl_u, aoff, boff0, boff1, (uint32_t)(ks0 * 32), fr[0]);
    #pragma unroll
    for (int s = 0; s < 8; ++s) {
        if (s < 7)
            ld_frags6(ah_u, al_u, bh_u, bl_u, aoff, boff0, boff1,
                      (uint32_t)((ks0 + s + 1) * 32), fr[(s + 1) & 1]);
        issue_mmas6(fr[s & 1], acc);
    }
}

// ---- 2-term fp16 inner loop: (Ahi+Alo)*Bhi ----
__device__ __forceinline__ void mma_steps8_f16(uint32_t ah_u, uint32_t al_u, uint32_t bh_u,
                                               int wm, int wn, int lane,
                                               int ks0, float acc[4][4]) {
    int a_row = wm * 16 + (lane & 15);
    int a_ko = (lane >> 4) << 3;
    uint32_t aoff = (uint32_t)((a_row * FAPITCH + a_ko) * 2);
    int b_row = wn * 32 + (lane & 7) + ((lane >> 4) << 3);
    int b_ko = ((lane >> 3) & 1) << 3;
    uint32_t boff0 = (uint32_t)((b_row * FAPITCH + b_ko) * 2);
    uint32_t boff1 = (uint32_t)(((b_row + 16) * FAPITCH + b_ko) * 2);

    uint32_t fr[2][4][4];
    {
        uint32_t kb2 = (uint32_t)(ks0 * 32);
        ldm_x4(fr[0][0], ah_u + aoff + kb2);
        ldm_x4(fr[0][1], al_u + aoff + kb2);
        ldm_x4(fr[0][2], bh_u + boff0 + kb2);
        ldm_x4(fr[0][3], bh_u + boff1 + kb2);
    }
    #pragma unroll
    for (int s = 0; s < 8; ++s) {
        if (s < 7) {
            uint32_t kb2 = (uint32_t)((ks0 + s + 1) * 32);
            int nb = (s + 1) & 1;
            ldm_x4(fr[nb][0], ah_u + aoff + kb2);
            ldm_x4(fr[nb][1], al_u + aoff + kb2);
            ldm_x4(fr[nb][2], bh_u + boff0 + kb2);
            ldm_x4(fr[nb][3], bh_u + boff1 + kb2);
        }
        uint32_t (*f)[4] = fr[s & 1];
        #pragma unroll
        for (int nf = 0; nf < 4; ++nf)
            mma_f16(acc[nf], f[0], &f[2 + (nf >> 1)][(nf & 1) * 2]);
        #pragma unroll
        for (int nf = 0; nf < 4; ++nf)
            mma_f16(acc[nf], f[1], &f[2 + (nf >> 1)][(nf & 1) * 2]);
    }
}

// ================= fused h GEMM + build =================
// blocks [0,128): h GEMM (masks consumed only in epilogue, gated by g_done spin)
// block 128: node top-k; block 129: edge top-k; block 130: incidence build
__global__ void __launch_bounds__(GT) k_gemm_h(const float* __restrict__ nf,
                                               const float* __restrict__ efi,
                                               const float* __restrict__ bias) {
    extern __shared__ __nv_bfloat16 smx[];
    int bx = blockIdx.x;
    int tid = threadIdx.x;

    if (bx >= 128) {
        int role = bx - 128;
        if (role < 2) build_topk(*(TkSmem*)smx, role);
        else          build_inc(*(IncSmem*)smx);
        return;
    }

    __nv_bfloat16* as_hi = smx + F_AHI;
    __nv_bfloat16* as_lo = smx + F_ALO;
    uint32_t base = (uint32_t)__cvta_generic_to_shared(smx);
    uint32_t ah_u = base + F_AHI * 2, al_u = base + F_ALO * 2;
    uint32_t bh_u = base + F_BHI * 2, bl_u = base + F_BLO * 2;

    int wid = tid >> 5, lane = tid & 31;
    int g = lane >> 2, t = lane & 3;
    int wm = wid >> 1, wn = wid & 1;
    int m0 = (bx >> 2) * 128, n0 = (bx & 3) * 64;

    cp_b_full(bh_u, bl_u, 0, n0, tid);
    cp_commit();
    #pragma unroll
    for (int it = 0; it < 16; ++it) {
        int idx = it * GT + tid;
        int m = idx >> 6, k4 = (idx & 63) * 4;
        int e = m0 + m;
        int a = g_src[e], b = g_dst[e];
        float4 xa = *(const float4*)&nf[(size_t)a * D + k4];
        float4 xb = *(const float4*)&nf[(size_t)b * D + k4];
        float4 s = {xa.x + xb.x, xa.y + xb.y, xa.z + xb.z, xa.w + xb.w};
        split_store_a(as_hi, as_lo, m * FAPITCH + k4, s);
    }
    cp_wait0();
    __syncthreads();

    float acc[4][4] = {};
    mma_steps8(ah_u, al_u, bh_u, bl_u, wm, wn, lane, 0, acc);
    mma_steps8(ah_u, al_u, bh_u, bl_u, wm, wn, lane, 8, acc);

    // wait for both top-k blocks (masks) — overlapped with all work above
    if (tid == 0) {
        volatile int* pf = &g_done;
        while (*pf < 2) { }
    }
    __syncthreads();
    __threadfence();

    int r0 = m0 + wm * 16 + g;
    #pragma unroll
    for (int half = 0; half < 2; ++half) {
        int r = r0 + half * 8;
        int em = g_emask[r] & g_nmask[g_src[r]] & g_nmask[g_dst[r]];
        float fm = em ? 1.0f : 0.0f;
        #pragma unroll
        for (int nf2 = 0; nf2 < 4; ++nf2) {
            int c = n0 + wn * 32 + nf2 * 8 + 2 * t;
            float v0 = acc[nf2][half * 2 + 0] + bias[c] + fm * efi[(size_t)r * D + c];
            float v1 = acc[nf2][half * 2 + 1] + bias[c + 1] + fm * efi[(size_t)r * D + c + 1];
            __nv_bfloat16 h0 = __float2bfloat16(v0), h1 = __float2bfloat16(v1);
            __nv_bfloat16 l0 = __float2bfloat16(v0 - __bfloat162float(h0));
            __nv_bfloat16 l1 = __float2bfloat16(v1 - __bfloat162float(h1));
            *(__nv_bfloat162*)&g_hhi[(size_t)r * D + c] = __nv_bfloat162(h0, h1);
            *(__nv_bfloat162*)&g_hlo[(size_t)r * D + c] = __nv_bfloat162(l0, l1);
        }
    }
}

// fused q/k/v GEMM: A resident once; B(w+1) prefetch overlaps epilogue(w)
__global__ void __launch_bounds__(GT) k_gemm_qkv(
        const float* __restrict__ bq, const float* __restrict__ bk,
        const float* __restrict__ bv) {
    extern __shared__ __nv_bfloat16 smx[];
    uint32_t base = (uint32_t)__cvta_generic_to_shared(smx);
    uint32_t ah_u = base + F_AHI * 2, al_u = base + F_ALO * 2;
    uint32_t bh_u = base + F_BHI * 2, bl_u = base + F_BLO * 2;

    int tid = threadIdx.x;
    int wid = tid >> 5, lane = tid & 31;
    int g = lane >> 2, t = lane & 3;
    int wm = wid >> 1, wn = wid & 1;
    int m0 = blockIdx.y * 128, n0 = blockIdx.x * 64;

    cp_b_full(bh_u, bl_u, 1, n0, tid);
    cp_a_half(ah_u, al_u, g_hhi, g_hlo, m0, tid, 0);
    cp_commit();
    cp_a_half(ah_u, al_u, g_hhi, g_hlo, m0, tid, 1);
    cp_commit();

    #pragma unroll
    for (int w = 0; w < 3; ++w) {
        float acc[4][4] = {};
        if (w == 0) {
            cp_wait1();
            __syncthreads();
            mma_steps8(ah_u, al_u, bh_u, bl_u, wm, wn, lane, 0, acc);
            cp_wait0();
            __syncthreads();
            mma_steps8(ah_u, al_u, bh_u, bl_u, wm, wn, lane, 8, acc);
        } else {
            mma_steps8(ah_u, al_u, bh_u, bl_u, wm, wn, lane, 0, acc);
            mma_steps8(ah_u, al_u, bh_u, bl_u, wm, wn, lane, 8, acc);
        }

        if (w < 2) {
            __syncthreads();
            cp_b_full(bh_u, bl_u, 2 + w, n0, tid);
            cp_commit();
        }

        const float* bias = (w == 0) ? bq : (w == 1) ? bk : bv;
        float* C = (w == 0) ? g_q : (w == 1) ? g_k : g_v;
        int r0 = m0 + wm * 16 + g;
        #pragma unroll
        for (int nf = 0; nf < 4; ++nf) {
            int c = n0 + wn * 32 + nf * 8 + 2 * t;
            float bb0 = bias[c], bb1 = bias[c + 1];
            #pragma unroll
            for (int half = 0; half < 2; ++half) {
                int r = r0 + half * 8;
                float2 o2 = {acc[nf][half * 2 + 0] + bb0,
                             acc[nf][half * 2 + 1] + bb1};
                *(float2*)&C[(size_t)r * D + c] = o2;
            }
        }
        if (w < 2) {
            cp_wait0();
            __syncthreads();
        }
    }
}

// 2-term fp16 GEMM: STAGE 0: o = ao@Wo + bo; STAGE 1: hid = gelu(o@W1 + b1)
template <int STAGE>
__global__ void __launch_bounds__(GT) k_gemm_f16k(const float* __restrict__ bias) {
    extern __shared__ __nv_bfloat16 smx[];
    uint32_t base = (uint32_t)__cvta_generic_to_shared(smx);
    uint32_t ah_u = base + F_AHI * 2, al_u = base + F_ALO * 2;
    uint32_t bh_u = base + F_BHI * 2;

    const __half* Ahi = (STAGE == 0) ? g_aohi : g_ohi;
    const __half* Alo = (STAGE == 0) ? g_aolo : g_olo;
    __half* Chi = (STAGE == 0) ? g_ohi : g_hidhi;
    __half* Clo = (STAGE == 0) ? g_olo : g_hidlo;
    const int wslot = (STAGE == 0) ? 4 : 5;

    int tid = threadIdx.x;
    int wid = tid >> 5, lane = tid & 31;
    int g = lane >> 2, t = lane & 3;
    int wm = wid >> 1, wn = wid & 1;
    int m0 = blockIdx.y * 128, n0 = blockIdx.x * 64;

    cp_b_hi(bh_u, wslot, n0, tid);
    cp_a_half(ah_u, al_u, Ahi, Alo, m0, tid, 0);
    cp_commit();
    cp_a_half(ah_u, al_u, Ahi, Alo, m0, tid, 1);
    cp_commit();

    float acc[4][4] = {};
    cp_wait1();
    __syncthreads();
    mma_steps8_f16(ah_u, al_u, bh_u, wm, wn, lane, 0, acc);
    cp_wait0();
    __syncthreads();
    mma_steps8_f16(ah_u, al_u, bh_u, wm, wn, lane, 8, acc);

    int r0 = m0 + wm * 16 + g;
    #pragma unroll
    for (int nf = 0; nf < 4; ++nf) {
        int c = n0 + wn * 32 + nf * 8 + 2 * t;
        float bb0 = bias[c], bb1 = bias[c + 1];
        #pragma unroll
        for (int half = 0; half < 2; ++half) {
            int r = r0 + half * 8;
            float v0 = acc[nf][half * 2 + 0] + bb0;
            float v1 = acc[nf][half * 2 + 1] + bb1;
            if (STAGE == 1) {
                float x0 = v0, x1 = v1;
                float t0 = tanhf(0.7978845608028654f * (x0 + 0.044715f * x0 * x0 * x0));
                float t1 = tanhf(0.7978845608028654f * (x1 + 0.044715f * x1 * x1 * x1));
                v0 = 0.5f * x0 * (1.0f + t0);
                v1 = 0.5f * x1 * (1.0f + t1);
            }
            __half h0 = __float2half(v0), h1 = __float2half(v1);
            __half l0 = __float2half(v0 - __half2float(h0));
            __half l1 = __float2half(v1 - __half2float(h1));
            *(__half2*)&Chi[(size_t)r * D + c] = __halves2half2(h0, h1);
            *(__half2*)&Clo[(size_t)r * D + c] = __halves2half2(l0, l1);
        }
    }
}

// ================= sparse masked attention (2-way ILP) =================
__global__ void k_attn() {
    __shared__ int s_cand[MAXC];
    __shared__ float s_sc[HN][MAXC];
    __shared__ int s_n;
    int e = blockIdx.x;
    int tid = threadIdx.x;
    int h = tid >> 5, lane = tid & 31;
    int a = g_src[e], b = g_dst[e];
    int oa = g_off[a];
    int na = g_off[a + 1] - oa;

    for (int i = tid; i < na; i += 128) s_cand[i] = g_inc[oa + i];

    if (tid < 32) {
        int cnt = na;
        if (b != a) {
            int ob = g_off[b];
            int nb = g_off[b + 1] - ob;
            for (int i0 = 0; i0 < nb; i0 += 32) {
                int i = i0 + lane;
                int f = 0, keep = 0;
                if (i < nb) {
                    f = g_inc[ob + i];
                    keep = (g_src[f] != a && g_dst[f] != a) ? 1 : 0;
                }
                unsigned bal = __ballot_sync(0xffffffffu, keep != 0);
                if (keep) {
                    int pos = cnt + __popc(bal & ((1u << lane) - 1u));
                    if (pos < MAXC) s_cand[pos] = f;
                }
                cnt += __popc(bal);
            }
        }
        if (lane == 0) s_n = (cnt < MAXC) ? cnt : MAXC;
    }
    __syncthreads();
    int nc = s_n;
    int base = e * D + h * DHD;

    float2 q2 = *(const float2*)&g_q[base + lane * 2];

    for (int c = 0; c < nc; c += 2) {
        int f0 = s_cand[c];
        float2 k0 = *(const float2*)&g_k[f0 * D + h * DHD + lane * 2];
        bool has1 = (c + 1 < nc);
        float2 k1 = {0.f, 0.f};
        if (has1) {
            int f1 = s_cand[c + 1];
            k1 = *(const float2*)&g_k[f1 * D + h * DHD + lane * 2];
        }
        float s0 = q2.x * k0.x + q2.y * k0.y;
        float s1 = q2.x * k1.x + q2.y * k1.y;
        #pragma unroll
        for (int o = 16; o; o >>= 1) {
            s0 += __shfl_xor_sync(0xffffffffu, s0, o);
            s1 += __shfl_xor_sync(0xffffffffu, s1, o);
        }
        if (lane == 0) {
            s_sc[h][c] = s0 * 0.125f;
            if (has1) s_sc[h][c + 1] = s1 * 0.125f;
        }
    }
    __syncwarp();

    float mx = -3.0e38f;
    for (int c = lane; c < nc; c += 32) mx = fmaxf(mx, s_sc[h][c]);
    #pragma unroll
    for (int o = 16; o; o >>= 1) mx = fmaxf(mx, __shfl_xor_sync(0xffffffffu, mx, o));
    float l = 0.f;
    for (int c = lane; c < nc; c += 32) {
        float p = __expf(s_sc[h][c] - mx);
        s_sc[h][c] = p;
        l += p;
    }
    #pragma unroll
    for (int o = 16; o; o >>= 1) l += __shfl_xor_sync(0xffffffffu, l, o);
    __syncwarp();

    float ax = 0.f, ay = 0.f;
    for (int c = 0; c < nc; c += 2) {
        float p0 = s_sc[h][c];
        float2 v0 = *(const float2*)&g_v[s_cand[c] * D + h * DHD + lane * 2];
        if (c + 1 < nc) {
            float p1 = s_sc[h][c + 1];
            float2 v1 = *(const float2*)&g_v[s_cand[c + 1] * D + h * DHD + lane * 2];
            ax += p0 * v0.x + p1 * v1.x;
            ay += p0 * v0.y + p1 * v1.y;
        } else {
            ax += p0 * v0.x;
            ay += p0 * v0.y;
        }
    }
    float inv = 1.f / l;
    float vx = ax * inv, vy = ay * inv;
    __half hx = __float2half(vx), hy = __float2half(vy);
    __half lx = __float2half(vx - __half2float(hx));
    __half ly = __float2half(vy - __half2float(hy));
    *(__half2*)&g_aohi[base + lane * 2] = __halves2half2(hx, hy);
    *(__half2*)&g_aolo[base + lane * 2] = __halves2half2(lx, ly);
}

// ================= classifier =================
__global__ void k_cls(const float* __restrict__ W2, const float* __restrict__ b2,
                      float* __restrict__ out) {
    int warp = (blockIdx.x * blockDim.x + threadIdx.x) >> 5;
    int lane = threadIdx.x & 31;
    if (warp >= NE) return;
    float x[8];
    #pragma unroll
    for (int i = 0; i < 8; ++i) {
        size_t id = (size_t)warp * D + lane + i * 32;
        x[i] = __half2float(g_hidhi[id]) + __half2float(g_hidlo[id]);
    }
    float res = 0.f;
    #pragma unroll
    for (int c = 0; c < CLS; ++c) {
        float s = 0.f;
        #pragma unroll
        for (int i = 0; i < 8; ++i) s += x[i] * W2[(size_t)(lane + i * 32) * CLS + c];
        #pragma unroll
        for (int o = 16; o; o >>= 1) s += __shfl_xor_sync(0xffffffffu, s, o);
        if (lane == c) res = s + b2[c];
    }
    if (lane < CLS) out[(size_t)warp * CLS + lane] = res;
}

// ================= host =================
extern "C" void kernel_launch(void* const* d_in, const int* in_sizes, int n_in,
                              void* d_out, int out_size) {
    const float* nf   = (const float*)d_in[0];
    const float* efi  = (const float*)d_in[1];
    const int*   ei   = (const int*)d_in[2];
    const float* Wn_r = (const float*)d_in[3];
    const float* bn_r = (const float*)d_in[4];
    const float* We_r = (const float*)d_in[5];
    const float* be_r = (const float*)d_in[6];
    const float* Wnp  = (const float*)d_in[7];
    const float* bnp  = (const float*)d_in[8];
    const float* Wq   = (const float*)d_in[9];
    const float* bq   = (const float*)d_in[10];
    const float* Wk   = (const float*)d_in[11];
    const float* bk   = (const float*)d_in[12];
    const float* Wv   = (const float*)d_in[13];
    const float* bv   = (const float*)d_in[14];
    const float* Wo   = (const float*)d_in[15];
    const float* bo   = (const float*)d_in[16];
    const float* W1   = (const float*)d_in[17];
    const float* b1   = (const float*)d_in[18];
    const float* W2   = (const float*)d_in[19];
    const float* b2   = (const float*)d_in[20];
    float* out = (float*)d_out;

    cudaFuncSetAttribute(k_gemm_h, cudaFuncAttributeMaxDynamicSharedMemorySize, F_BYTES);
    cudaFuncSetAttribute(k_gemm_qkv, cudaFuncAttributeMaxDynamicSharedMemorySize, F_BYTES);
    cudaFuncSetAttribute(k_gemm_f16k<0>, cudaFuncAttributeMaxDynamicSharedMemorySize, F_BYTES);
    cudaFuncSetAttribute(k_gemm_f16k<1>, cudaFuncAttributeMaxDynamicSharedMemorySize, F_BYTES);

    k_front<<<752, 256>>>(nf, efi, ei, Wn_r, bn_r, We_r, be_r, Wnp, Wq, Wk, Wv, Wo, W1);

    dim3 gg(D / 64, NE / 128);      // (4, 32) = 128 CTAs: one wave
    // fused: h GEMM (128 blocks) + topk x2 + incidence (3 blocks), co-resident
    k_gemm_h<<<131, GT, F_BYTES>>>(nf, efi, bnp);
    k_gemm_qkv<<<gg, GT, F_BYTES>>>(bq, bk, bv);             // q,k,v fp32 (3-term bf16)
    k_attn<<<NE, 128>>>();                                   // ao (fp16 split)
    k_gemm_f16k<0><<<gg, GT, F_BYTES>>>(bo);                 // o = ao@Wo (2-term fp16)
    k_gemm_f16k<1><<<gg, GT, F_BYTES>>>(b1);                 // hid = gelu(o@W1) (2-term fp16)
    k_cls<<<(NE * 32 + 255) / 256, 256>>>(W2, b2, out);
}

// round 17
// speedup vs baseline: 1.1555x; 1.0786x over previous
#include <cuda_runtime.h>
#include <cuda_bf16.h>
#include <cuda_fp16.h>
#include <math.h>
#include <stdint.h>

#define NN    1024
#define NE    4096
#define D     256
#define HN    4
#define DHD   64
#define NODEK 512
#define EDGEK 2048
#define CLS   16
#define MAXC  320

// full-K resident GEMM: CTA 128x64 tile, K=256, 16 warps (8m x 2n), warp 16x32
#define FAPITCH 264
#define F_AHI 0
#define F_ALO (128 * FAPITCH)
#define F_BHI (2 * 128 * FAPITCH)
#define F_BLO (2 * 128 * FAPITCH + 64 * FAPITCH)
#define F_ELEMS (2 * 128 * FAPITCH + 2 * 64 * FAPITCH)
#define F_BYTES (F_ELEMS * 2)   // 202752 B -> 1 CTA/SM
#define GT 512                  // GEMM CTA threads (16 warps)

// ---------------- scratch ----------------
__device__ int   g_done;
__device__ float g_nscore[NN];
__device__ float g_escore[NE];
__device__ int   g_nmask[NN];
__device__ int   g_emask[NE];
__device__ int   g_src[NE], g_dst[NE];
__device__ int   g_off[NN + 1];
__device__ int   g_inc[2 * NE];
__device__ float g_q[NE * D];
__device__ float g_k[NE * D];
__device__ float g_v[NE * D];
// split activations: h in bf16 (3-term qkv), ao/o/hid in fp16 (2-term path)
__device__ __nv_bfloat16 g_hhi[NE * D], g_hlo[NE * D];
__device__ __half g_aohi[NE * D], g_aolo[NE * D];
__device__ __half g_ohi[NE * D],  g_olo[NE * D];
__device__ __half g_hidhi[NE * D], g_hidlo[NE * D];
// transposed split weights: [w][n][k]; slots 0-3 bf16 hi/lo, slots 4-5 fp16 hi/lo
__device__ __nv_bfloat16 g_wthi[6 * D * D];
__device__ __nv_bfloat16 g_wtlo[6 * D * D];

// ================= build smem layouts (live in dynamic smem of fused kernel) =================
struct TkSmem {
    unsigned su[NE];
    int hist[256];
    unsigned pref;
    int krem;
    int wagg[32];
};
struct IncSmem {
    int cnt[NN];
    int off[NN];
    int pos[NN];
    int inc[2 * NE];
};

// ================= 1: fused front-end =================
__global__ void k_front(const float* __restrict__ nf, const float* __restrict__ efi,
                        const int* __restrict__ ei,
                        const float* __restrict__ Wn, const float* __restrict__ bn,
                        const float* __restrict__ We, const float* __restrict__ be,
                        const float* __restrict__ Wnp, const float* __restrict__ Wq,
                        const float* __restrict__ Wk, const float* __restrict__ Wv,
                        const float* __restrict__ Wo, const float* __restrict__ W1) {
    int b = blockIdx.x;
    int tid = threadIdx.x;
    if (b == 0 && tid == 0) g_done = 0;
    if (b < 96) {
        __shared__ float s[64][65];
        int w = b >> 4, t16 = b & 15;
        const float* W;
        switch (w) {
            case 0: W = Wnp; break;
            case 1: W = Wq; break;
            case 2: W = Wk; break;
            case 3: W = Wv; break;
            case 4: W = Wo; break;
            default: W = W1; break;
        }
        int n0 = (t16 & 3) * 64, k0 = (t16 >> 2) * 64;
        int n4 = (tid & 15) * 4, kr = tid >> 4;
        #pragma unroll
        for (int kk = kr; kk < 64; kk += 16) {
            float4 v = *(const float4*)&W[(size_t)(k0 + kk) * D + n0 + n4];
            s[kk][n4] = v.x;
            s[kk][n4 + 1] = v.y;
            s[kk][n4 + 2] = v.z;
            s[kk][n4 + 3] = v.w;
        }
        __syncthreads();
        int nl = tid >> 2, kq = (tid & 3) * 16;
        unsigned short hi[16], lo[16];
        #pragma unroll
        for (int i = 0; i < 16; ++i) {
            float x = s[kq + i][nl];
            if (w < 4) {
                __nv_bfloat16 h = __float2bfloat16(x);
                __nv_bfloat16 l = __float2bfloat16(x - __bfloat162float(h));
                hi[i] = *(unsigned short*)&h;
                lo[i] = *(unsigned short*)&l;
            } else {
                __half h = __float2half(x);
                __half l = __float2half(x - __half2float(h));
                hi[i] = *(unsigned short*)&h;
                lo[i] = *(unsigned short*)&l;
            }
        }
        size_t off = (size_t)w * D * D + (size_t)(n0 + nl) * D + k0 + kq;
        unsigned short* WH = (unsigned short*)g_wthi;
        unsigned short* WL = (unsigned short*)g_wtlo;
        *(uint4*)&WH[off] = *(uint4*)&hi[0];
        *(uint4*)&WH[off + 8] = *(uint4*)&hi[8];
        *(uint4*)&WL[off] = *(uint4*)&lo[0];
        *(uint4*)&WL[off + 8] = *(uint4*)&lo[8];
    } else if (b < 112) {
        __shared__ int sh[256];
        int acc = 0;
        for (int i = tid; i < 2048; i += 256) acc |= ei[2 * i + 1];
        sh[tid] = acc;
        __syncthreads();
        for (int s2 = 128; s2 > 0; s2 >>= 1) {
            if (tid < s2) sh[tid] |= sh[tid + s2];
            __syncthreads();
        }
        int is64 = (sh[0] == 0) ? 1 : 0;
        int i = (b - 96) * 256 + tid;
        int s, d;
        if (is64) { s = ei[2 * i]; d = ei[2 * (NE + i)]; }
        else      { s = ei[i];     d = ei[NE + i]; }
        g_src[i] = s;
        g_dst[i] = d;
    } else {
        int warp = (b - 112) * 8 + (tid >> 5);
        int lane = tid & 31;
        const float* x;
        const float* w;
        if (warp < NN) { x = nf + (size_t)warp * D; w = Wn; }
        else           { x = efi + (size_t)(warp - NN) * D; w = We; }
        float s = 0.f;
        #pragma unroll
        for (int i = 0; i < D / 32; ++i) s += x[lane + i * 32] * w[lane + i * 32];
        #pragma unroll
        for (int o = 16; o; o >>= 1) s += __shfl_xor_sync(0xffffffffu, s, o);
        if (lane == 0) {
            if (warp < NN) g_nscore[warp] = s + bn[0];
            else           g_escore[warp - NN] = s + be[0];
        }
    }
}

// ================= build bodies (512 threads) =================
__device__ void build_topk(TkSmem& tk, int role) {
    int tid = threadIdx.x;
    int lane = tid & 31, wid = tid >> 5;
    const bool is_edge = (role == 1);
    const float* sc = is_edge ? g_escore : g_nscore;
    int* mask = is_edge ? g_emask : g_nmask;
    const int n = is_edge ? NE : NN;
    const int kk = is_edge ? EDGEK : NODEK;
    int items = n >> 9;

    for (int j = 0; j < items; ++j) {
        int i = tid * items + j;
        unsigned bb = __float_as_uint(sc[i]);
        tk.su[i] = (bb & 0x80000000u) ? ~bb : (bb | 0x80000000u);
    }
    if (tid == 0) { tk.pref = 0u; tk.krem = kk; }
    __syncthreads();

    for (int shift = 24; shift >= 0; shift -= 8) {
        unsigned prefix = tk.pref;
        unsigned done_mask = (shift == 24) ? 0u : (0xFFFFFFFFu << (shift + 8));
        if (tid < 256) tk.hist[tid] = 0;
        __syncthreads();
        for (int j = 0; j < items; ++j) {
            unsigned u = tk.su[tid * items + j];
            if ((u & done_mask) == prefix)
                atomicAdd(&tk.hist[(u >> shift) & 255], 1);
        }
        __syncthreads();
        if (wid == 0) {
            int krem = tk.krem;
            int gsum = 0;
            #pragma unroll
            for (int c = 0; c < 8; ++c) gsum += tk.hist[lane * 8 + c];
            int x = gsum;
            #pragma unroll
            for (int off = 1; off < 32; off <<= 1) {
                int t = __shfl_down_sync(0xffffffffu, x, off);
                if (lane + off < 32) x += t;
            }
            int above = x - gsum;
            bool hit = (above < krem) && (x >= krem);
            unsigned bal = __ballot_sync(0xffffffffu, hit);
            int srcl = __ffs(bal) - 1;
            if (lane == srcl) {
                int cum = above;
                #pragma unroll
                for (int c = 7; c >= 0; --c) {
                    int bb = lane * 8 + c;
                    int hc = tk.hist[bb];
                    if (cum + hc >= krem) {
                        tk.pref = prefix | ((unsigned)bb << shift);
                        tk.krem = krem - cum;
                        break;
                    }
                    cum += hc;
                }
            }
        }
        __syncthreads();
    }
    unsigned T = tk.pref;
    int r = tk.krem;

    int ct = 0;
    for (int j = 0; j < items; ++j) ct += (tk.su[tid * items + j] == T) ? 1 : 0;
    int scan = ct;
    #pragma unroll
    for (int off = 1; off < 32; off <<= 1) {
        int t = __shfl_up_sync(0xffffffffu, scan, off);
        if (lane >= off) scan += t;
    }
    if (lane == 31) tk.wagg[wid] = scan;
    __syncthreads();
    if (wid == 0) {
        int v = (lane < 16) ? tk.wagg[lane] : 0;
        #pragma unroll
        for (int off = 1; off < 32; off <<= 1) {
            int t = __shfl_up_sync(0xffffffffu, v, off);
            if (lane >= off) v += t;
        }
        if (lane < 16) tk.wagg[lane] = v;
    }
    __syncthreads();
    int excl = (wid > 0 ? tk.wagg[wid - 1] : 0) + scan - ct;

    for (int j = 0; j < items; ++j) {
        int i = tid * items + j;
        unsigned u = tk.su[i];
        int mk;
        if (u > T) mk = 1;
        else if (u == T) { mk = (excl < r) ? 1 : 0; excl++; }
        else mk = 0;
        mask[i] = mk;
    }
    __threadfence();
    __syncthreads();
    if (tid == 0) atomicAdd(&g_done, 1);
}

__device__ void build_inc(IncSmem& in) {
    int tid = threadIdx.x;
    in.cnt[tid] = 0;
    in.cnt[tid + 512] = 0;
    __syncthreads();
    #pragma unroll
    for (int j = 0; j < 8; ++j) {
        int e = j * 512 + tid;
        int a = g_src[e], b = g_dst[e];
        atomicAdd(&in.cnt[a], 1);
        if (b != a) atomicAdd(&in.cnt[b], 1);
    }
    __syncthreads();
    int c0 = in.cnt[2 * tid], c1 = in.cnt[2 * tid + 1];
    in.off[tid] = c0 + c1;
    __syncthreads();
    int val = in.off[tid];
    for (int dd = 1; dd < 512; dd <<= 1) {
        int t = (tid >= dd) ? in.off[tid - dd] : 0;
        __syncthreads();
        val += t;
        in.off[tid] = val;
        __syncthreads();
    }
    int exclPair = val - (c0 + c1);
    __syncthreads();
    in.pos[2 * tid] = exclPair;
    in.pos[2 * tid + 1] = exclPair + c0;
    in.cnt[2 * tid] = exclPair;
    in.cnt[2 * tid + 1] = exclPair + c0;
    g_off[2 * tid] = exclPair;
    g_off[2 * tid + 1] = exclPair + c0;
    if (tid == 511) g_off[1024] = val;
    __syncthreads();
    int total = in.off[511];
    #pragma unroll
    for (int j = 0; j < 8; ++j) {
        int e = j * 512 + tid;
        int a = g_src[e], b = g_dst[e];
        in.inc[atomicAdd(&in.pos[a], 1)] = e;
        if (b != a) in.inc[atomicAdd(&in.pos[b], 1)] = e;
    }
    __syncthreads();
    #pragma unroll
    for (int q = 0; q < 2; ++q) {
        int node = q * 512 + tid;
        int s = in.cnt[node], t = in.pos[node];
        for (int i = s + 1; i < t; ++i) {
            int v = in.inc[i];
            int j = i - 1;
            while (j >= s && in.inc[j] > v) { in.inc[j + 1] = in.inc[j]; --j; }
            in.inc[j + 1] = v;
        }
    }
    __syncthreads();
    for (int i = tid; i < total; i += 512) g_inc[i] = in.inc[i];
}

// ================= GEMM primitives =================
__device__ __forceinline__ void mma_bf16(float* c, const uint32_t* a, const uint32_t* b) {
    asm volatile(
        "mma.sync.aligned.m16n8k16.row.col.f32.bf16.bf16.f32 "
        "{%0,%1,%2,%3}, {%4,%5,%6,%7}, {%8,%9}, {%0,%1,%2,%3};"
        : "+f"(c[0]), "+f"(c[1]), "+f"(c[2]), "+f"(c[3])
        : "r"(a[0]), "r"(a[1]), "r"(a[2]), "r"(a[3]), "r"(b[0]), "r"(b[1]));
}
__device__ __forceinline__ void mma_f16(float* c, const uint32_t* a, const uint32_t* b) {
    asm volatile(
        "mma.sync.aligned.m16n8k16.row.col.f32.f16.f16.f32 "
        "{%0,%1,%2,%3}, {%4,%5,%6,%7}, {%8,%9}, {%0,%1,%2,%3};"
        : "+f"(c[0]), "+f"(c[1]), "+f"(c[2]), "+f"(c[3])
        : "r"(a[0]), "r"(a[1]), "r"(a[2]), "r"(a[3]), "r"(b[0]), "r"(b[1]));
}

__device__ __forceinline__ void ldm_x4(uint32_t* r, uint32_t addr) {
    asm volatile("ldmatrix.sync.aligned.m8n8.x4.shared.b16 {%0,%1,%2,%3}, [%4];"
                 : "=r"(r[0]), "=r"(r[1]), "=r"(r[2]), "=r"(r[3]) : "r"(addr));
}

__device__ __forceinline__ void cp16(uint32_t s, const void* g) {
    asm volatile("cp.async.cg.shared.global [%0], [%1], 16;" :: "r"(s), "l"(g));
}
__device__ __forceinline__ void cp_commit() {
    asm volatile("cp.async.commit_group;" ::: "memory");
}
__device__ __forceinline__ void cp_wait0() {
    asm volatile("cp.async.wait_group 0;" ::: "memory");
}
__device__ __forceinline__ void cp_wait1() {
    asm volatile("cp.async.wait_group 1;" ::: "memory");
}

__device__ __forceinline__ void split_store_a(__nv_bfloat16* as_hi, __nv_bfloat16* as_lo,
                                              int o, float4 a) {
    __nv_bfloat16 h0 = __float2bfloat16(a.x), h1 = __float2bfloat16(a.y);
    __nv_bfloat16 h2 = __float2bfloat16(a.z), h3 = __float2bfloat16(a.w);
    __nv_bfloat16 l0 = __float2bfloat16(a.x - __bfloat162float(h0));
    __nv_bfloat16 l1 = __float2bfloat16(a.y - __bfloat162float(h1));
    __nv_bfloat16 l2 = __float2bfloat16(a.z - __bfloat162float(h2));
    __nv_bfloat16 l3 = __float2bfloat16(a.w - __bfloat162float(h3));
    *(__nv_bfloat162*)&as_hi[o]     = __nv_bfloat162(h0, h1);
    *(__nv_bfloat162*)&as_hi[o + 2] = __nv_bfloat162(h2, h3);
    *(__nv_bfloat162*)&as_lo[o]     = __nv_bfloat162(l0, l1);
    *(__nv_bfloat162*)&as_lo[o + 2] = __nv_bfloat162(l2, l3);
}

template <typename T>
__device__ __forceinline__ void cp_a_half(uint32_t ah_u, uint32_t al_u,
                                          const T* Ahi, const T* Alo,
                                          int m0, int tid, int kh) {
    int kb = kh * 128;
    #pragma unroll
    for (int it = 0; it < 4; ++it) {
        int idx = it * GT + tid;
        int m = idx >> 4, kq = kb + (idx & 15) * 8;
        uint32_t so = (uint32_t)((m * FAPITCH + kq) * 2);
        cp16(ah_u + so, &Ahi[(size_t)(m0 + m) * D + kq]);
        cp16(al_u + so, &Alo[(size_t)(m0 + m) * D + kq]);
    }
}

__device__ __forceinline__ void cp_b_full(uint32_t bh_u, uint32_t bl_u,
                                          int wslot, int n0, int tid) {
    const __nv_bfloat16* Bh = g_wthi + (size_t)wslot * D * D;
    const __nv_bfloat16* Bl = g_wtlo + (size_t)wslot * D * D;
    #pragma unroll
    for (int it = 0; it < 4; ++it) {
        int idx = it * GT + tid;
        int n = idx >> 5, kq = (idx & 31) * 8;
        uint32_t so = (uint32_t)((n * FAPITCH + kq) * 2);
        cp16(bh_u + so, &Bh[(size_t)(n0 + n) * D + kq]);
        cp16(bl_u + so, &Bl[(size_t)(n0 + n) * D + kq]);
    }
}

__device__ __forceinline__ void cp_b_hi(uint32_t bh_u, int wslot, int n0, int tid) {
    const unsigned short* Bh = (const unsigned short*)g_wthi + (size_t)wslot * D * D;
    #pragma unroll
    for (int it = 0; it < 2; ++it) {
        int idx = it * GT + tid;
        int n = idx >> 4, kq = (idx & 15) * 16;
        uint32_t so = (uint32_t)((n * FAPITCH + kq) * 2);
        cp16(bh_u + so, &Bh[(size_t)(n0 + n) * D + kq]);
        cp16(bh_u + so + 16, &Bh[(size_t)(n0 + n) * D + kq + 8]);
    }
}

// ---- 3-term bf16 inner loop ----
__device__ __forceinline__ void ld_frags6(uint32_t ah_u, uint32_t al_u,
                                          uint32_t bh_u, uint32_t bl_u,
                                          uint32_t aoff, uint32_t boff0, uint32_t boff1,
                                          uint32_t kb2, uint32_t f[6][4]) {
    ldm_x4(f[0], ah_u + aoff + kb2);
    ldm_x4(f[1], al_u + aoff + kb2);
    ldm_x4(f[2], bh_u + boff0 + kb2);
    ldm_x4(f[3], bh_u + boff1 + kb2);
    ldm_x4(f[4], bl_u + boff0 + kb2);
    ldm_x4(f[5], bl_u + boff1 + kb2);
}

__device__ __forceinline__ void issue_mmas6(uint32_t f[6][4], float acc[4][4]) {
    #pragma unroll
    for (int nf = 0; nf < 4; ++nf)
        mma_bf16(acc[nf], f[0], &f[2 + (nf >> 1)][(nf & 1) * 2]);
    #pragma unroll
    for (int nf = 0; nf < 4; ++nf)
        mma_bf16(acc[nf], f[0], &f[4 + (nf >> 1)][(nf & 1) * 2]);
    #pragma unroll
    for (int nf = 0; nf < 4; ++nf)
        mma_bf16(acc[nf], f[1], &f[2 + (nf >> 1)][(nf & 1) * 2]);
}

__device__ __forceinline__ void mma_steps8(uint32_t ah_u, uint32_t al_u,
                                           uint32_t bh_u, uint32_t bl_u,
                                           int wm, int wn, int lane,
                                           int ks0, float acc[4][4]) {
    int a_row = wm * 16 + (lane & 15);
    int a_ko = (lane >> 4) << 3;
    uint32_t aoff = (uint32_t)((a_row * FAPITCH + a_ko) * 2);
    int b_row = wn * 32 + (lane & 7) + ((lane >> 4) << 3);
    int b_ko = ((lane >> 3) & 1) << 3;
    uint32_t boff0 = (uint32_t)((b_row * FAPITCH + b_ko) * 2);
    uint32_t boff1 = (uint32_t)(((b_row + 16) * FAPITCH + b_ko) * 2);

    uint32_t fr[2][6][4];
    ld_frags6(ah_u, al_u, bh_u, bl_u, aoff, boff0, boff1, (uint32_t)(ks0 * 32), fr[0]);
    #pragma unroll
    for (int s = 0; s < 8; ++s) {
        if (s < 7)
            ld_frags6(ah_u, al_u, bh_u, bl_u, aoff, boff0, boff1,
                      (uint32_t)((ks0 + s + 1) * 32), fr[(s + 1) & 1]);
        issue_mmas6(fr[s & 1], acc);
    }
}

// ---- 2-term fp16 inner loop ----
__device__ __forceinline__ void mma_steps8_f16(uint32_t ah_u, uint32_t al_u, uint32_t bh_u,
                                               int wm, int wn, int lane,
                                               int ks0, float acc[4][4]) {
    int a_row = wm * 16 + (lane & 15);
    int a_ko = (lane >> 4) << 3;
    uint32_t aoff = (uint32_t)((a_row * FAPITCH + a_ko) * 2);
    int b_row = wn * 32 + (lane & 7) + ((lane >> 4) << 3);
    int b_ko = ((lane >> 3) & 1) << 3;
    uint32_t boff0 = (uint32_t)((b_row * FAPITCH + b_ko) * 2);
    uint32_t boff1 = (uint32_t)(((b_row + 16) * FAPITCH + b_ko) * 2);

    uint32_t fr[2][4][4];
    {
        uint32_t kb2 = (uint32_t)(ks0 * 32);
        ldm_x4(fr[0][0], ah_u + aoff + kb2);
        ldm_x4(fr[0][1], al_u + aoff + kb2);
        ldm_x4(fr[0][2], bh_u + boff0 + kb2);
        ldm_x4(fr[0][3], bh_u + boff1 + kb2);
    }
    #pragma unroll
    for (int s = 0; s < 8; ++s) {
        if (s < 7) {
            uint32_t kb2 = (uint32_t)((ks0 + s + 1) * 32);
            int nb = (s + 1) & 1;
            ldm_x4(fr[nb][0], ah_u + aoff + kb2);
            ldm_x4(fr[nb][1], al_u + aoff + kb2);
            ldm_x4(fr[nb][2], bh_u + boff0 + kb2);
            ldm_x4(fr[nb][3], bh_u + boff1 + kb2);
        }
        uint32_t (*f)[4] = fr[s & 1];
        #pragma unroll
        for (int nf = 0; nf < 4; ++nf)
            mma_f16(acc[nf], f[0], &f[2 + (nf >> 1)][(nf & 1) * 2]);
        #pragma unroll
        for (int nf = 0; nf < 4; ++nf)
            mma_f16(acc[nf], f[1], &f[2 + (nf >> 1)][(nf & 1) * 2]);
    }
}

// ================= fused h GEMM + build =================
__global__ void __launch_bounds__(GT) k_gemm_h(const float* __restrict__ nf,
                                               const float* __restrict__ efi,
                                               const float* __restrict__ bias) {
    extern __shared__ __nv_bfloat16 smx[];
    int bx = blockIdx.x;
    int tid = threadIdx.x;

    if (bx >= 128) {
        int role = bx - 128;
        if (role < 2) build_topk(*(TkSmem*)smx, role);
        else          build_inc(*(IncSmem*)smx);
        return;
    }

    __nv_bfloat16* as_hi = smx + F_AHI;
    __nv_bfloat16* as_lo = smx + F_ALO;
    uint32_t base = (uint32_t)__cvta_generic_to_shared(smx);
    uint32_t ah_u = base + F_AHI * 2, al_u = base + F_ALO * 2;
    uint32_t bh_u = base + F_BHI * 2, bl_u = base + F_BLO * 2;

    int wid = tid >> 5, lane = tid & 31;
    int g = lane >> 2, t = lane & 3;
    int wm = wid >> 1, wn = wid & 1;
    int m0 = (bx >> 2) * 128, n0 = (bx & 3) * 64;

    cp_b_full(bh_u, bl_u, 0, n0, tid);
    cp_commit();
    #pragma unroll
    for (int it = 0; it < 16; ++it) {
        int idx = it * GT + tid;
        int m = idx >> 6, k4 = (idx & 63) * 4;
        int e = m0 + m;
        int a = g_src[e], b = g_dst[e];
        float4 xa = *(const float4*)&nf[(size_t)a * D + k4];
        float4 xb = *(const float4*)&nf[(size_t)b * D + k4];
        float4 s = {xa.x + xb.x, xa.y + xb.y, xa.z + xb.z, xa.w + xb.w};
        split_store_a(as_hi, as_lo, m * FAPITCH + k4, s);
    }
    cp_wait0();
    __syncthreads();

    float acc[4][4] = {};
    mma_steps8(ah_u, al_u, bh_u, bl_u, wm, wn, lane, 0, acc);
    mma_steps8(ah_u, al_u, bh_u, bl_u, wm, wn, lane, 8, acc);

    if (tid == 0) {
        volatile int* pf = &g_done;
        while (*pf < 2) { }
    }
    __syncthreads();
    __threadfence();

    int r0 = m0 + wm * 16 + g;
    #pragma unroll
    for (int half = 0; half < 2; ++half) {
        int r = r0 + half * 8;
        int em = g_emask[r] & g_nmask[g_src[r]] & g_nmask[g_dst[r]];
        float fm = em ? 1.0f : 0.0f;
        #pragma unroll
        for (int nf2 = 0; nf2 < 4; ++nf2) {
            int c = n0 + wn * 32 + nf2 * 8 + 2 * t;
            float v0 = acc[nf2][half * 2 + 0] + bias[c] + fm * efi[(size_t)r * D + c];
            float v1 = acc[nf2][half * 2 + 1] + bias[c + 1] + fm * efi[(size_t)r * D + c + 1];
            __nv_bfloat16 h0 = __float2bfloat16(v0), h1 = __float2bfloat16(v1);
            __nv_bfloat16 l0 = __float2bfloat16(v0 - __bfloat162float(h0));
            __nv_bfloat16 l1 = __float2bfloat16(v1 - __bfloat162float(h1));
            *(__nv_bfloat162*)&g_hhi[(size_t)r * D + c] = __nv_bfloat162(h0, h1);
            *(__nv_bfloat162*)&g_hlo[(size_t)r * D + c] = __nv_bfloat162(l0, l1);
        }
    }
}

// fused q/k/v GEMM
__global__ void __launch_bounds__(GT) k_gemm_qkv(
        const float* __restrict__ bq, const float* __restrict__ bk,
        const float* __restrict__ bv) {
    extern __shared__ __nv_bfloat16 smx[];
    uint32_t base = (uint32_t)__cvta_generic_to_shared(smx);
    uint32_t ah_u = base + F_AHI * 2, al_u = base + F_ALO * 2;
    uint32_t bh_u = base + F_BHI * 2, bl_u = base + F_BLO * 2;

    int tid = threadIdx.x;
    int wid = tid >> 5, lane = tid & 31;
    int g = lane >> 2, t = lane & 3;
    int wm = wid >> 1, wn = wid & 1;
    int m0 = blockIdx.y * 128, n0 = blockIdx.x * 64;

    cp_b_full(bh_u, bl_u, 1, n0, tid);
    cp_a_half(ah_u, al_u, g_hhi, g_hlo, m0, tid, 0);
    cp_commit();
    cp_a_half(ah_u, al_u, g_hhi, g_hlo, m0, tid, 1);
    cp_commit();

    #pragma unroll
    for (int w = 0; w < 3; ++w) {
        float acc[4][4] = {};
        if (w == 0) {
            cp_wait1();
            __syncthreads();
            mma_steps8(ah_u, al_u, bh_u, bl_u, wm, wn, lane, 0, acc);
            cp_wait0();
            __syncthreads();
            mma_steps8(ah_u, al_u, bh_u, bl_u, wm, wn, lane, 8, acc);
        } else {
            mma_steps8(ah_u, al_u, bh_u, bl_u, wm, wn, lane, 0, acc);
            mma_steps8(ah_u, al_u, bh_u, bl_u, wm, wn, lane, 8, acc);
        }

        if (w < 2) {
            __syncthreads();
            cp_b_full(bh_u, bl_u, 2 + w, n0, tid);
            cp_commit();
        }

        const float* bias = (w == 0) ? bq : (w == 1) ? bk : bv;
        float* C = (w == 0) ? g_q : (w == 1) ? g_k : g_v;
        int r0 = m0 + wm * 16 + g;
        #pragma unroll
        for (int nf = 0; nf < 4; ++nf) {
            int c = n0 + wn * 32 + nf * 8 + 2 * t;
            float bb0 = bias[c], bb1 = bias[c + 1];
            #pragma unroll
            for (int half = 0; half < 2; ++half) {
                int r = r0 + half * 8;
                float2 o2 = {acc[nf][half * 2 + 0] + bb0,
                             acc[nf][half * 2 + 1] + bb1};
                *(float2*)&C[(size_t)r * D + c] = o2;
            }
        }
        if (w < 2) {
            cp_wait0();
            __syncthreads();
        }
    }
}

// 2-term fp16 GEMM
template <int STAGE>
__global__ void __launch_bounds__(GT) k_gemm_f16k(const float* __restrict__ bias) {
    extern __shared__ __nv_bfloat16 smx[];
    uint32_t base = (uint32_t)__cvta_generic_to_shared(smx);
    uint32_t ah_u = base + F_AHI * 2, al_u = base + F_ALO * 2;
    uint32_t bh_u = base + F_BHI * 2;

    const __half* Ahi = (STAGE == 0) ? g_aohi : g_ohi;
    const __half* Alo = (STAGE == 0) ? g_aolo : g_olo;
    __half* Chi = (STAGE == 0) ? g_ohi : g_hidhi;
    __half* Clo = (STAGE == 0) ? g_olo : g_hidlo;
    const int wslot = (STAGE == 0) ? 4 : 5;

    int tid = threadIdx.x;
    int wid = tid >> 5, lane = tid & 31;
    int g = lane >> 2, t = lane & 3;
    int wm = wid >> 1, wn = wid & 1;
    int m0 = blockIdx.y * 128, n0 = blockIdx.x * 64;

    cp_b_hi(bh_u, wslot, n0, tid);
    cp_a_half(ah_u, al_u, Ahi, Alo, m0, tid, 0);
    cp_commit();
    cp_a_half(ah_u, al_u, Ahi, Alo, m0, tid, 1);
    cp_commit();

    float acc[4][4] = {};
    cp_wait1();
    __syncthreads();
    mma_steps8_f16(ah_u, al_u, bh_u, wm, wn, lane, 0, acc);
    cp_wait0();
    __syncthreads();
    mma_steps8_f16(ah_u, al_u, bh_u, wm, wn, lane, 8, acc);

    int r0 = m0 + wm * 16 + g;
    #pragma unroll
    for (int nf = 0; nf < 4; ++nf) {
        int c = n0 + wn * 32 + nf * 8 + 2 * t;
        float bb0 = bias[c], bb1 = bias[c + 1];
        #pragma unroll
        for (int half = 0; half < 2; ++half) {
            int r = r0 + half * 8;
            float v0 = acc[nf][half * 2 + 0] + bb0;
            float v1 = acc[nf][half * 2 + 1] + bb1;
            if (STAGE == 1) {
                float x0 = v0, x1 = v1;
                float t0 = tanhf(0.7978845608028654f * (x0 + 0.044715f * x0 * x0 * x0));
                float t1 = tanhf(0.7978845608028654f * (x1 + 0.044715f * x1 * x1 * x1));
                v0 = 0.5f * x0 * (1.0f + t0);
                v1 = 0.5f * x1 * (1.0f + t1);
            }
            __half h0 = __float2half(v0), h1 = __float2half(v1);
            __half l0 = __float2half(v0 - __half2float(h0));
            __half l1 = __float2half(v1 - __half2float(h1));
            *(__half2*)&Chi[(size_t)r * D + c] = __halves2half2(h0, h1);
            *(__half2*)&Clo[(size_t)r * D + c] = __halves2half2(l0, l1);
        }
    }
}

// ================= sparse masked attention (8-lane-per-candidate scores) =================
__global__ void k_attn() {
    __shared__ int s_cand[MAXC];
    __shared__ float s_sc[HN][MAXC];
    __shared__ int s_n;
    int e = blockIdx.x;
    int tid = threadIdx.x;
    int h = tid >> 5, lane = tid & 31;
    int a = g_src[e], b = g_dst[e];
    int oa = g_off[a];
    int na = g_off[a + 1] - oa;

    for (int i = tid; i < na; i += 128) s_cand[i] = g_inc[oa + i];

    if (tid < 32) {
        int cnt = na;
        if (b != a) {
            int ob = g_off[b];
            int nb = g_off[b + 1] - ob;
            for (int i0 = 0; i0 < nb; i0 += 32) {
                int i = i0 + lane;
                int f = 0, keep = 0;
                if (i < nb) {
                    f = g_inc[ob + i];
                    keep = (g_src[f] != a && g_dst[f] != a) ? 1 : 0;
                }
                unsigned bal = __ballot_sync(0xffffffffu, keep != 0);
                if (keep) {
                    int pos = cnt + __popc(bal & ((1u << lane) - 1u));
                    if (pos < MAXC) s_cand[pos] = f;
                }
                cnt += __popc(bal);
            }
        }
        if (lane == 0) s_n = (cnt < MAXC) ? cnt : MAXC;
    }
    __syncthreads();
    int nc = s_n;
    int base = e * D + h * DHD;

    // scores: 8 lanes per candidate, 4 candidates per warp iteration.
    // lane = 8*j + i: j = candidate slot (0..3), i = dim chunk (0..7, 8 dims each)
    int i8 = lane & 7, j4 = lane >> 3;
    float4 q0 = *(const float4*)&g_q[base + i8 * 8];
    float4 q1 = *(const float4*)&g_q[base + i8 * 8 + 4];
    for (int c0 = 0; c0 < nc; c0 += 4) {
        int cc = c0 + j4;
        float s = 0.f;
        if (cc < nc) {
            int f = s_cand[cc];
            const float* kp = &g_k[f * D + h * DHD + i8 * 8];
            float4 k0 = *(const float4*)kp;
            float4 k1 = *(const float4*)(kp + 4);
            s = q0.x * k0.x + q0.y * k0.y + q0.z * k0.z + q0.w * k0.w
              + q1.x * k1.x + q1.y * k1.y + q1.z * k1.z + q1.w * k1.w;
        }
        #pragma unroll
        for (int o = 4; o; o >>= 1) s += __shfl_xor_sync(0xffffffffu, s, o);
        if (i8 == 0 && cc < nc) s_sc[h][cc] = s * 0.125f;
    }
    __syncwarp();

    float mx = -3.0e38f;
    for (int c = lane; c < nc; c += 32) mx = fmaxf(mx, s_sc[h][c]);
    #pragma unroll
    for (int o = 16; o; o >>= 1) mx = fmaxf(mx, __shfl_xor_sync(0xffffffffu, mx, o));
    float l = 0.f;
    for (int c = lane; c < nc; c += 32) {
        float p = __expf(s_sc[h][c] - mx);
        s_sc[h][c] = p;
        l += p;
    }
    #pragma unroll
    for (int o = 16; o; o >>= 1) l += __shfl_xor_sync(0xffffffffu, l, o);
    __syncwarp();

    // weighted V sum: 4-way unrolled gather
    float ax = 0.f, ay = 0.f;
    int c = 0;
    for (; c + 4 <= nc; c += 4) {
        float p0 = s_sc[h][c], p1 = s_sc[h][c + 1];
        float p2 = s_sc[h][c + 2], p3 = s_sc[h][c + 3];
        float2 v0 = *(const float2*)&g_v[s_cand[c] * D + h * DHD + lane * 2];
        float2 v1 = *(const float2*)&g_v[s_cand[c + 1] * D + h * DHD + lane * 2];
        float2 v2 = *(const float2*)&g_v[s_cand[c + 2] * D + h * DHD + lane * 2];
        float2 v3 = *(const float2*)&g_v[s_cand[c + 3] * D + h * DHD + lane * 2];
        ax += p0 * v0.x + p1 * v1.x + p2 * v2.x + p3 * v3.x;
        ay += p0 * v0.y + p1 * v1.y + p2 * v2.y + p3 * v3.y;
    }
    for (; c < nc; ++c) {
        float p = s_sc[h][c];
        float2 v = *(const float2*)&g_v[s_cand[c] * D + h * DHD + lane * 2];
        ax += p * v.x;
        ay += p * v.y;
    }
    float inv = 1.f / l;
    float vx = ax * inv, vy = ay * inv;
    __half hx = __float2half(vx), hy = __float2half(vy);
    __half lx = __float2half(vx - __half2float(hx));
    __half ly = __float2half(vy - __half2float(hy));
    *(__half2*)&g_aohi[base + lane * 2] = __halves2half2(hx, hy);
    *(__half2*)&g_aolo[base + lane * 2] = __halves2half2(lx, ly);
}

// ================= classifier =================
__global__ void k_cls(const float* __restrict__ W2, const float* __restrict__ b2,
                      float* __restrict__ out) {
    int warp = (blockIdx.x * blockDim.x + threadIdx.x) >> 5;
    int lane = threadIdx.x & 31;
    if (warp >= NE) return;
    float x[8];
    #pragma unroll
    for (int i = 0; i < 8; ++i) {
        size_t id = (size_t)warp * D + lane + i * 32;
        x[i] = __half2float(g_hidhi[id]) + __half2float(g_hidlo[id]);
    }
    float res = 0.f;
    #pragma unroll
    for (int c = 0; c < CLS; ++c) {
        float s = 0.f;
        #pragma unroll
        for (int i = 0; i < 8; ++i) s += x[i] * W2[(size_t)(lane + i * 32) * CLS + c];
        #pragma unroll
        for (int o = 16; o; o >>= 1) s += __shfl_xor_sync(0xffffffffu, s, o);
        if (lane == c) res = s + b2[c];
    }
    if (lane < CLS) out[(size_t)warp * CLS + lane] = res;
}

// ================= host =================
extern "C" void kernel_launch(void* const* d_in, const int* in_sizes, int n_in,
                              void* d_out, int out_size) {
    const float* nf   = (const float*)d_in[0];
    const float* efi  = (const float*)d_in[1];
    const int*   ei   = (const int*)d_in[2];
    const float* Wn_r = (const float*)d_in[3];
    const float* bn_r = (const float*)d_in[4];
    const float* We_r = (const float*)d_in[5];
    const float* be_r = (const float*)d_in[6];
    const float* Wnp  = (const float*)d_in[7];
    const float* bnp  = (const float*)d_in[8];
    const float* Wq   = (const float*)d_in[9];
    const float* bq   = (const float*)d_in[10];
    const float* Wk   = (const float*)d_in[11];
    const float* bk   = (const float*)d_in[12];
    const float* Wv   = (const float*)d_in[13];
    const float* bv   = (const float*)d_in[14];
    const float* Wo   = (const float*)d_in[15];
    const float* bo   = (const float*)d_in[16];
    const float* W1   = (const float*)d_in[17];
    const float* b1   = (const float*)d_in[18];
    const float* W2   = (const float*)d_in[19];
    const float* b2   = (const float*)d_in[20];
    float* out = (float*)d_out;

    cudaFuncSetAttribute(k_gemm_h, cudaFuncAttributeMaxDynamicSharedMemorySize, F_BYTES);
    cudaFuncSetAttribute(k_gemm_qkv, cudaFuncAttributeMaxDynamicSharedMemorySize, F_BYTES);
    cudaFuncSetAttribute(k_gemm_f16k<0>, cudaFuncAttributeMaxDynamicSharedMemorySize, F_BYTES);
    cudaFuncSetAttribute(k_gemm_f16k<1>, cudaFuncAttributeMaxDynamicSharedMemorySize, F_BYTES);

    k_front<<<752, 256>>>(nf, efi, ei, Wn_r, bn_r, We_r, be_r, Wnp, Wq, Wk, Wv, Wo, W1);

    dim3 gg(D / 64, NE / 128);      // (4, 32) = 128 CTAs: one wave
    k_gemm_h<<<131, GT, F_BYTES>>>(nf, efi, bnp);            // h GEMM + topk + incidence
    k_gemm_qkv<<<gg, GT, F_BYTES>>>(bq, bk, bv);             // q,k,v fp32 (3-term bf16)
    k_attn<<<NE, 128>>>();                                   // ao (fp16 split)
    k_gemm_f16k<0><<<gg, GT, F_BYTES>>>(bo);                 // o = ao@Wo (2-term fp16)
    k_gemm_f16k<1><<<gg, GT, F_BYTES>>>(b1);                 // hid = gelu(o@W1) (2-term fp16)
    k_cls<<<(NE * 32 + 255) / 256, 256>>>(W2, b2, out);
}